// round 7
// baseline (speedup 1.0000x reference)
#include <cuda_runtime.h>
#include <cuda_fp16.h>
#include <cstdint>

#define MAXN 50000
#define MAXE 1600000
#define FIN  48
#define HID  32
#define NCLS 10
#define KS   4
#define NB   16

// ---------------- scratch (device globals) --------------------------------------
__device__ __half    g_xw1h[MAXN * KS * HID];   // [N][4][32] fp16
__device__ float     g_rb1 [MAXN * HID];        // x@root1 + bias1 (fp32)
__device__ __half    g_xw2h[MAXN * KS * NCLS];  // [N][4][10] fp16
__device__ float     g_rb2 [MAXN * NCLS];
__device__ float     g_agg1[MAXN * HID];
__device__ float     g_agg2[MAXN * NCLS];
__device__ float     g_h   [MAXN * HID];
__device__ float     g_deg [MAXN];
__device__ uint2     g_pack[MAXE];              // x: src|dst<<16,  y: frac-bits|k0
__device__ int       g_is64;

// ---------------- helpers ---------------------------------------------------------
__device__ __forceinline__ void red_add_v4(float* addr, float4 v) {
    asm volatile("red.global.add.v4.f32 [%0], {%1,%2,%3,%4};"
                 :: "l"(addr), "f"(v.x), "f"(v.y), "f"(v.z), "f"(v.w) : "memory");
}
__device__ __forceinline__ void red_add_v2(float* addr, float2 v) {
    asm volatile("red.global.add.v2.f32 [%0], {%1,%2};"
                 :: "l"(addr), "f"(v.x), "f"(v.y) : "memory");
}
__device__ __forceinline__ unsigned long long pack2(float w) {
    unsigned long long r;
    asm("mov.b64 %0, {%1, %1};" : "=l"(r) : "f"(w));
    return r;
}
__device__ __forceinline__ void ffma2(unsigned long long& d, unsigned long long a,
                                      unsigned long long b) {
    asm("fma.rn.f32x2 %0, %1, %2, %0;" : "+l"(d) : "l"(a), "l"(b));
}
__device__ __forceinline__ float2 unpack2(unsigned long long v) {
    float lo, hi;
    asm("mov.b64 {%0, %1}, %2;" : "=f"(lo), "=f"(hi) : "l"(v));
    return make_float2(lo, hi);
}

// ---------------- dtype detection -------------------------------------------------
__global__ void k_detect(const void* __restrict__ ei) {
    int i = threadIdx.x;
    int hi = ((const int*)ei)[2 * i + 1];
    unsigned b = __ballot_sync(0xffffffffu, hi != 0);
    if (i == 0) g_is64 = (b == 0) ? 1 : 0;
}

// ---------------- zero agg1, agg2, deg --------------------------------------------
__global__ void k_zero(int N) {
    int tot = N * (HID + NCLS + 1);
    for (int i = blockIdx.x * blockDim.x + threadIdx.x; i < tot; i += gridDim.x * blockDim.x) {
        if (i < N * HID)               g_agg1[i] = 0.f;
        else if (i < N * (HID + NCLS)) g_agg2[i - N * HID] = 0.f;
        else                           g_deg[i - N * (HID + NCLS)] = 0.f;
    }
}

// ---------------- pack edges: decode once, also accumulate degree ------------------
__global__ void __launch_bounds__(256) k_pack(const void* __restrict__ ei,
                                              const float* __restrict__ ea, int E) {
    int e = blockIdx.x * blockDim.x + threadIdx.x;
    if (e >= E) return;
    int src, dst;
    if (g_is64) {
        src = (int)((const long long*)ei)[e];
        dst = (int)((const long long*)ei)[(long long)E + e];
    } else {
        src = ((const int*)ei)[e];
        dst = ((const int*)ei)[E + e];
    }
    float u = ea[e];
    float vv = u * (float)(KS - 1);
    float vf = floorf(vv);
    float frac = vv - vf;
    int k0 = min(max((int)vf, 0), KS - 1);
    g_pack[e] = make_uint2((unsigned)src | ((unsigned)dst << 16),
                           (__float_as_uint(frac) & ~3u) | (unsigned)k0);
    atomicAdd(&g_deg[dst], 1.0f);
}

// ---------------- layer-1 node GEMM: f32x2 column-pairs, W plain in smem ----------
// warp w -> cols [20w, 20w+20); lane -> node; thread: 10 col-pair f32x2 accs.
__global__ void __launch_bounds__(256) k_xw1(const float* __restrict__ x,
                                             const float* __restrict__ W1,
                                             const float* __restrict__ root1,
                                             const float* __restrict__ bias1, int N) {
    __shared__ __align__(16) float Ws[FIN * 160];
    for (int i = threadIdx.x; i < FIN * 160; i += 256) {
        int f = i / 160, j = i % 160;
        Ws[i] = (j < 128) ? W1[(((j >> 5) * FIN) + f) * HID + (j & 31)]
                          : root1[f * HID + (j - 128)];
    }
    __syncthreads();
    const int warp = threadIdx.x >> 5;
    const int lane = threadIdx.x & 31;
    const int col0 = warp * 20;
    int ntiles = (N + 31) / 32;
    for (int tile = blockIdx.x; tile < ntiles; tile += gridDim.x) {
        int n = tile * 32 + lane;
        int nc = min(n, N - 1);
        float xr[FIN];
        #pragma unroll
        for (int q = 0; q < FIN / 4; q++) {
            float4 v = *(const float4*)&x[nc * FIN + q * 4];
            xr[q*4] = v.x; xr[q*4+1] = v.y; xr[q*4+2] = v.z; xr[q*4+3] = v.w;
        }
        unsigned long long acc2[10];
        #pragma unroll
        for (int i = 0; i < 10; i++) acc2[i] = 0ull;
        #pragma unroll
        for (int f = 0; f < FIN; f++) {
            unsigned long long xd = pack2(xr[f]);
            const ulonglong2* wrow = (const ulonglong2*)&Ws[f * 160 + col0];
            #pragma unroll
            for (int c = 0; c < 5; c++) {
                ulonglong2 wv = wrow[c];
                ffma2(acc2[2*c],     wv.x, xd);
                ffma2(acc2[2*c + 1], wv.y, xd);
            }
        }
        if (n < N) {
            #pragma unroll
            for (int i = 0; i < 10; i++) {
                int col = col0 + 2 * i;
                float2 v = unpack2(acc2[i]);
                if (col < 128) {
                    *(__half2*)&g_xw1h[n * 128 + col] = __floats2half2_rn(v.x, v.y);
                } else {
                    int o = col - 128;
                    float2 b = *(const float2*)&bias1[o];
                    *(float2*)&g_rb1[n * HID + o] = make_float2(v.x + b.x, v.y + b.y);
                }
            }
        }
    }
}

// ---------------- layer-1 edge scatter: 8 lanes/edge, fp16 gather, fp32 red -------
__global__ void __launch_bounds__(256) k_edge1(int E) {
    long long t = (long long)blockIdx.x * blockDim.x + threadIdx.x;
    long long e = t >> 3;
    int f4 = (int)(t & 7);
    if (e >= E) return;
    uint2 r = g_pack[e];
    int src = r.x & 0xffff;
    int dst = r.x >> 16;
    int k0  = r.y & 3;
    int k1  = min(k0 + 1, KS - 1);
    float f = __uint_as_float(r.y & ~3u);
    const __half* base = g_xw1h + src * 128;
    uint2 pa = *(const uint2*)(base + k0 * 32 + f4 * 4);
    uint2 pb = *(const uint2*)(base + k1 * 32 + f4 * 4);
    float2 A0 = __half22float2(*(const __half2*)&pa.x);
    float2 A1 = __half22float2(*(const __half2*)&pa.y);
    float2 B0 = __half22float2(*(const __half2*)&pb.x);
    float2 B1 = __half22float2(*(const __half2*)&pb.y);
    float w0 = 1.0f - f;
    float4 m = make_float4(w0 * A0.x + f * B0.x, w0 * A0.y + f * B0.y,
                           w0 * A1.x + f * B1.x, w0 * A1.y + f * B1.y);
    red_add_v4(&g_agg1[dst * HID + f4 * 4], m);
}

// ---------------- layer-1 epilogue: h = elu(agg1/deg + rb1) ------------------------
__global__ void k_h(int N) {
    int i = blockIdx.x * blockDim.x + threadIdx.x;
    if (i >= N * HID) return;
    int n = i >> 5;
    float d = fmaxf(g_deg[n], 1.0f);
    float v = g_agg1[i] / d + g_rb1[i];
    g_h[i] = (v > 0.f) ? v : expm1f(v);
}

// ---------------- layer-2 node GEMM (f32x2, warp-per-column) -----------------------
__global__ void __launch_bounds__(64) k_prep2(const float* __restrict__ W2,
                                              const float* __restrict__ root2,
                                              const float* __restrict__ bias2, int N) {
    const int j = threadIdx.x;          // active j<50
    bool active = (j < 50);
    float wcol[HID];
    float binit = 0.f;
    if (j < 40) {
        int k = j / NCLS, c = j % NCLS;
        #pragma unroll
        for (int o = 0; o < HID; o++) wcol[o] = W2[(k * HID + o) * NCLS + c];
    } else if (j < 50) {
        int c = j - 40;
        #pragma unroll
        for (int o = 0; o < HID; o++) wcol[o] = root2[o * NCLS + c];
        binit = bias2[c];
    }
    __shared__ __align__(16) float hs[HID * NB];
    int ntiles = (N + NB - 1) / NB;
    for (int tile = blockIdx.x; tile < ntiles; tile += gridDim.x) {
        int n0 = tile * NB;
        __syncthreads();
        for (int idx = j; idx < HID * NB; idx += 64) {
            int nn = idx / HID, o = idx % HID;
            int n = n0 + nn;
            hs[o * NB + nn] = (n < N) ? g_h[n * HID + o] : 0.f;
        }
        __syncthreads();
        if (active) {
            unsigned long long acc2[NB / 2];
            unsigned long long binit2 = pack2(binit);
            #pragma unroll
            for (int p = 0; p < NB / 2; p++) acc2[p] = binit2;
            #pragma unroll
            for (int o = 0; o < HID; o++) {
                unsigned long long w2 = pack2(wcol[o]);
                #pragma unroll
                for (int q = 0; q < NB / 4; q++) {
                    ulonglong2 hv = *(const ulonglong2*)&hs[o * NB + q * 4];
                    ffma2(acc2[q * 2],     hv.x, w2);
                    ffma2(acc2[q * 2 + 1], hv.y, w2);
                }
            }
            #pragma unroll
            for (int p = 0; p < NB / 2; p++) {
                float2 v = unpack2(acc2[p]);
                int na = n0 + p * 2, nb2 = na + 1;
                if (na < N) {
                    if (j < 40) g_xw2h[na * 40 + j]         = __float2half(v.x);
                    else        g_rb2[na * NCLS + (j - 40)] = v.x;
                }
                if (nb2 < N) {
                    if (j < 40) g_xw2h[nb2 * 40 + j]         = __float2half(v.y);
                    else        g_rb2[nb2 * NCLS + (j - 40)] = v.y;
                }
            }
        }
    }
}

// ---------------- layer-2 edge scatter: 6 edges/warp x 5 lanes (float2) -----------
__global__ void __launch_bounds__(256) k_edge2(int E) {
    int t = blockIdx.x * blockDim.x + threadIdx.x;
    int lane = t & 31;
    int wid = t >> 5;
    int eg = lane / 5;
    int j  = lane - eg * 5;
    if (eg >= 6) return;
    long long e = (long long)wid * 6 + eg;
    if (e >= E) return;
    uint2 r = g_pack[e];
    int src = r.x & 0xffff;
    int dst = r.x >> 16;
    int k0  = r.y & 3;
    int k1  = min(k0 + 1, KS - 1);
    float f = __uint_as_float(r.y & ~3u);
    const __half* base = g_xw2h + src * 40;
    unsigned pa = *(const unsigned*)(base + k0 * 10 + j * 2);
    unsigned pb = *(const unsigned*)(base + k1 * 10 + j * 2);
    float2 A = __half22float2(*(const __half2*)&pa);
    float2 B = __half22float2(*(const __half2*)&pb);
    float w0 = 1.0f - f;
    float2 m = make_float2(w0 * A.x + f * B.x, w0 * A.y + f * B.y);
    red_add_v2(&g_agg2[dst * NCLS + j * 2], m);
}

// ---------------- final: mean + root + bias + log_softmax -------------------------
__global__ void k_out(float* __restrict__ out, int N) {
    int n = blockIdx.x * blockDim.x + threadIdx.x;
    if (n >= N) return;
    float inv = 1.0f / fmaxf(g_deg[n], 1.0f);
    float v[NCLS];
    float mx = -1e30f;
    #pragma unroll
    for (int c = 0; c < NCLS; c++) {
        v[c] = g_agg2[n * NCLS + c] * inv + g_rb2[n * NCLS + c];
        mx = fmaxf(mx, v[c]);
    }
    float s = 0.f;
    #pragma unroll
    for (int c = 0; c < NCLS; c++) s += expf(v[c] - mx);
    float ls = logf(s) + mx;
    #pragma unroll
    for (int c = 0; c < NCLS; c++) out[n * NCLS + c] = v[c] - ls;
}

// ---------------- launch -----------------------------------------------------------
extern "C" void kernel_launch(void* const* d_in, const int* in_sizes, int n_in,
                              void* d_out, int out_size) {
    const float* x     = (const float*)d_in[0];
    const void*  ei    =               d_in[1];
    const float* ea    = (const float*)d_in[2];
    const float* W1    = (const float*)d_in[3];
    const float* root1 = (const float*)d_in[4];
    const float* bias1 = (const float*)d_in[5];
    const float* W2    = (const float*)d_in[6];
    const float* root2 = (const float*)d_in[7];
    const float* bias2 = (const float*)d_in[8];
    float* out = (float*)d_out;

    int N = in_sizes[0] / FIN;     // 50000
    int E = in_sizes[2];           // 1600000

    k_detect<<<1, 32>>>(ei);
    k_zero<<<(N * (HID + NCLS + 1) + 255) / 256, 256>>>(N);
    k_pack<<<(E + 255) / 256, 256>>>(ei, ea, E);
    k_xw1<<<592, 256>>>(x, W1, root1, bias1, N);
    long long th1 = (long long)E * 8;
    k_edge1<<<(int)((th1 + 255) / 256), 256>>>(E);
    k_h<<<(N * HID + 255) / 256, 256>>>(N);
    k_prep2<<<1184, 64>>>(W2, root2, bias2, N);
    int warps2 = (E + 5) / 6;
    k_edge2<<<(warps2 + 7) / 8, 256>>>(E);
    k_out<<<(N + 255) / 256, 256>>>(out, N);
}

// round 8
// speedup vs baseline: 2.8371x; 2.8371x over previous
#include <cuda_runtime.h>
#include <cuda_fp16.h>
#include <cstdint>

#define MAXN 50000
#define MAXE 1600000
#define FIN  48
#define HID  32
#define NCLS 10
#define KS   4
#define NB   16

// ---------------- scratch (device globals) --------------------------------------
__device__ __half    g_xw1h[MAXN * KS * HID];   // [N][4][32] fp16
__device__ float     g_rb1 [MAXN * HID];        // x@root1 + bias1 (fp32)
__device__ __half    g_xw2h[MAXN * KS * NCLS];  // [N][4][10] fp16
__device__ float     g_rb2 [MAXN * NCLS];
__device__ float     g_agg1[MAXN * HID];
__device__ float     g_agg2[MAXN * NCLS];
__device__ float     g_h   [MAXN * HID];
__device__ float     g_deg [MAXN];
__device__ uint2     g_pack[MAXE];              // x: src|dst<<16,  y: frac-bits|k0
__device__ int       g_is64;

// ---------------- helpers ---------------------------------------------------------
__device__ __forceinline__ void red_add_v4(float* addr, float4 v) {
    asm volatile("red.global.add.v4.f32 [%0], {%1,%2,%3,%4};"
                 :: "l"(addr), "f"(v.x), "f"(v.y), "f"(v.z), "f"(v.w) : "memory");
}
__device__ __forceinline__ void red_add_v2(float* addr, float2 v) {
    asm volatile("red.global.add.v2.f32 [%0], {%1,%2};"
                 :: "l"(addr), "f"(v.x), "f"(v.y) : "memory");
}
__device__ __forceinline__ unsigned long long pack2(float w) {
    unsigned long long r;
    asm("mov.b64 %0, {%1, %1};" : "=l"(r) : "f"(w));
    return r;
}
__device__ __forceinline__ void ffma2(unsigned long long& d, unsigned long long a,
                                      unsigned long long b) {
    asm("fma.rn.f32x2 %0, %1, %2, %0;" : "+l"(d) : "l"(a), "l"(b));
}
__device__ __forceinline__ float2 unpack2(unsigned long long v) {
    float lo, hi;
    asm("mov.b64 {%0, %1}, %2;" : "=f"(lo), "=f"(hi) : "l"(v));
    return make_float2(lo, hi);
}

// ---------------- dtype detection -------------------------------------------------
__global__ void k_detect(const void* __restrict__ ei) {
    int i = threadIdx.x;
    int hi = ((const int*)ei)[2 * i + 1];
    unsigned b = __ballot_sync(0xffffffffu, hi != 0);
    if (i == 0) g_is64 = (b == 0) ? 1 : 0;
}

// ---------------- zero agg1, agg2, deg --------------------------------------------
__global__ void k_zero(int N) {
    int tot = N * (HID + NCLS + 1);
    for (int i = blockIdx.x * blockDim.x + threadIdx.x; i < tot; i += gridDim.x * blockDim.x) {
        if (i < N * HID)               g_agg1[i] = 0.f;
        else if (i < N * (HID + NCLS)) g_agg2[i - N * HID] = 0.f;
        else                           g_deg[i - N * (HID + NCLS)] = 0.f;
    }
}

// ---------------- pack edges: decode once, also accumulate degree ------------------
__global__ void __launch_bounds__(256) k_pack(const void* __restrict__ ei,
                                              const float* __restrict__ ea, int E) {
    int e = blockIdx.x * blockDim.x + threadIdx.x;
    if (e >= E) return;
    int src, dst;
    if (g_is64) {
        src = (int)((const long long*)ei)[e];
        dst = (int)((const long long*)ei)[(long long)E + e];
    } else {
        src = ((const int*)ei)[e];
        dst = ((const int*)ei)[E + e];
    }
    float u = ea[e];
    float vv = u * (float)(KS - 1);
    float vf = floorf(vv);
    float frac = vv - vf;
    int k0 = min(max((int)vf, 0), KS - 1);
    g_pack[e] = make_uint2((unsigned)src | ((unsigned)dst << 16),
                           (__float_as_uint(frac) & ~3u) | (unsigned)k0);
    atomicAdd(&g_deg[dst], 1.0f);
}

// ---------------- layer-1 node GEMM: f32x2 column-pairs, x AND W in smem ----------
// warp w -> cols [20w, 20w+20); lane -> node within 32-node tile.
__global__ void __launch_bounds__(256) k_xw1(const float* __restrict__ x,
                                             const float* __restrict__ W1,
                                             const float* __restrict__ root1,
                                             const float* __restrict__ bias1, int N) {
    __shared__ __align__(16) float Ws[FIN * 160];   // 30720 B
    __shared__ float xs[32 * 49];                   // 6272 B, padded stride 49
    for (int i = threadIdx.x; i < FIN * 160; i += 256) {
        int f = i / 160, j = i % 160;
        Ws[i] = (j < 128) ? W1[(((j >> 5) * FIN) + f) * HID + (j & 31)]
                          : root1[f * HID + (j - 128)];
    }
    const int warp = threadIdx.x >> 5;
    const int lane = threadIdx.x & 31;
    const int col0 = warp * 20;
    int ntiles = (N + 31) / 32;
    for (int tile = blockIdx.x; tile < ntiles; tile += gridDim.x) {
        __syncthreads();
        // coalesced fill of x tile (contiguous 32*48 floats)
        long long base = (long long)tile * 32 * FIN;
        for (int idx = threadIdx.x; idx < 32 * FIN; idx += 256) {
            int nn = idx / FIN, f = idx % FIN;
            long long gi = base + idx;
            xs[nn * 49 + f] = (gi < (long long)N * FIN) ? x[gi] : 0.f;
        }
        __syncthreads();
        unsigned long long acc2[10];
        #pragma unroll
        for (int i = 0; i < 10; i++) acc2[i] = 0ull;
        const float* xrow = &xs[lane * 49];
        #pragma unroll
        for (int f = 0; f < FIN; f++) {
            unsigned long long xd = pack2(xrow[f]);
            const ulonglong2* wrow = (const ulonglong2*)&Ws[f * 160 + col0];
            #pragma unroll
            for (int c = 0; c < 5; c++) {
                ulonglong2 wv = wrow[c];
                ffma2(acc2[2*c],     wv.x, xd);
                ffma2(acc2[2*c + 1], wv.y, xd);
            }
        }
        int n = tile * 32 + lane;
        if (n < N) {
            #pragma unroll
            for (int i = 0; i < 10; i++) {
                int col = col0 + 2 * i;
                float2 v = unpack2(acc2[i]);
                if (col < 128) {
                    *(__half2*)&g_xw1h[n * 128 + col] = __floats2half2_rn(v.x, v.y);
                } else {
                    int o = col - 128;
                    float2 b = *(const float2*)&bias1[o];
                    *(float2*)&g_rb1[n * HID + o] = make_float2(v.x + b.x, v.y + b.y);
                }
            }
        }
    }
}

// ---------------- layer-1 edge scatter: 8 lanes/edge, fp16 gather, fp32 red -------
__global__ void __launch_bounds__(256) k_edge1(int E) {
    long long t = (long long)blockIdx.x * blockDim.x + threadIdx.x;
    long long e = t >> 3;
    int f4 = (int)(t & 7);
    if (e >= E) return;
    uint2 r = g_pack[e];
    int src = r.x & 0xffff;
    int dst = r.x >> 16;
    int k0  = r.y & 3;
    int k1  = min(k0 + 1, KS - 1);
    float f = __uint_as_float(r.y & ~3u);
    const __half* base = g_xw1h + src * 128;
    uint2 pa = *(const uint2*)(base + k0 * 32 + f4 * 4);
    uint2 pb = *(const uint2*)(base + k1 * 32 + f4 * 4);
    float2 A0 = __half22float2(*(const __half2*)&pa.x);
    float2 A1 = __half22float2(*(const __half2*)&pa.y);
    float2 B0 = __half22float2(*(const __half2*)&pb.x);
    float2 B1 = __half22float2(*(const __half2*)&pb.y);
    float w0 = 1.0f - f;
    float4 m = make_float4(w0 * A0.x + f * B0.x, w0 * A0.y + f * B0.y,
                           w0 * A1.x + f * B1.x, w0 * A1.y + f * B1.y);
    red_add_v4(&g_agg1[dst * HID + f4 * 4], m);
}

// ---------------- layer-1 epilogue: h = elu(agg1/deg + rb1) ------------------------
__global__ void k_h(int N) {
    int i = blockIdx.x * blockDim.x + threadIdx.x;
    if (i >= N * HID) return;
    int n = i >> 5;
    float d = fmaxf(g_deg[n], 1.0f);
    float v = g_agg1[i] / d + g_rb1[i];
    g_h[i] = (v > 0.f) ? v : expm1f(v);
}

// ---------------- layer-2 node GEMM (f32x2, warp-per-column) -----------------------
__global__ void __launch_bounds__(64) k_prep2(const float* __restrict__ W2,
                                              const float* __restrict__ root2,
                                              const float* __restrict__ bias2, int N) {
    const int j = threadIdx.x;          // active j<50
    bool active = (j < 50);
    float wcol[HID];
    float binit = 0.f;
    if (j < 40) {
        int k = j / NCLS, c = j % NCLS;
        #pragma unroll
        for (int o = 0; o < HID; o++) wcol[o] = W2[(k * HID + o) * NCLS + c];
    } else if (j < 50) {
        int c = j - 40;
        #pragma unroll
        for (int o = 0; o < HID; o++) wcol[o] = root2[o * NCLS + c];
        binit = bias2[c];
    }
    __shared__ __align__(16) float hs[HID * NB];
    int ntiles = (N + NB - 1) / NB;
    for (int tile = blockIdx.x; tile < ntiles; tile += gridDim.x) {
        int n0 = tile * NB;
        __syncthreads();
        for (int idx = j; idx < HID * NB; idx += 64) {
            int nn = idx / HID, o = idx % HID;
            int n = n0 + nn;
            hs[o * NB + nn] = (n < N) ? g_h[n * HID + o] : 0.f;
        }
        __syncthreads();
        if (active) {
            unsigned long long acc2[NB / 2];
            unsigned long long binit2 = pack2(binit);
            #pragma unroll
            for (int p = 0; p < NB / 2; p++) acc2[p] = binit2;
            #pragma unroll
            for (int o = 0; o < HID; o++) {
                unsigned long long w2 = pack2(wcol[o]);
                #pragma unroll
                for (int q = 0; q < NB / 4; q++) {
                    ulonglong2 hv = *(const ulonglong2*)&hs[o * NB + q * 4];
                    ffma2(acc2[q * 2],     hv.x, w2);
                    ffma2(acc2[q * 2 + 1], hv.y, w2);
                }
            }
            #pragma unroll
            for (int p = 0; p < NB / 2; p++) {
                float2 v = unpack2(acc2[p]);
                int na = n0 + p * 2, nb2 = na + 1;
                if (na < N) {
                    if (j < 40) g_xw2h[na * 40 + j]         = __float2half(v.x);
                    else        g_rb2[na * NCLS + (j - 40)] = v.x;
                }
                if (nb2 < N) {
                    if (j < 40) g_xw2h[nb2 * 40 + j]         = __float2half(v.y);
                    else        g_rb2[nb2 * NCLS + (j - 40)] = v.y;
                }
            }
        }
    }
}

// ---------------- layer-2 edge scatter: 6 edges/warp x 5 lanes (float2) -----------
__global__ void __launch_bounds__(256) k_edge2(int E) {
    int t = blockIdx.x * blockDim.x + threadIdx.x;
    int lane = t & 31;
    int wid = t >> 5;
    int eg = lane / 5;
    int j  = lane - eg * 5;
    if (eg >= 6) return;
    long long e = (long long)wid * 6 + eg;
    if (e >= E) return;
    uint2 r = g_pack[e];
    int src = r.x & 0xffff;
    int dst = r.x >> 16;
    int k0  = r.y & 3;
    int k1  = min(k0 + 1, KS - 1);
    float f = __uint_as_float(r.y & ~3u);
    const __half* base = g_xw2h + src * 40;
    unsigned pa = *(const unsigned*)(base + k0 * 10 + j * 2);
    unsigned pb = *(const unsigned*)(base + k1 * 10 + j * 2);
    float2 A = __half22float2(*(const __half2*)&pa);
    float2 B = __half22float2(*(const __half2*)&pb);
    float w0 = 1.0f - f;
    float2 m = make_float2(w0 * A.x + f * B.x, w0 * A.y + f * B.y);
    red_add_v2(&g_agg2[dst * NCLS + j * 2], m);
}

// ---------------- final: mean + root + bias + log_softmax -------------------------
__global__ void k_out(float* __restrict__ out, int N) {
    int n = blockIdx.x * blockDim.x + threadIdx.x;
    if (n >= N) return;
    float inv = 1.0f / fmaxf(g_deg[n], 1.0f);
    float v[NCLS];
    float mx = -1e30f;
    #pragma unroll
    for (int c = 0; c < NCLS; c++) {
        v[c] = g_agg2[n * NCLS + c] * inv + g_rb2[n * NCLS + c];
        mx = fmaxf(mx, v[c]);
    }
    float s = 0.f;
    #pragma unroll
    for (int c = 0; c < NCLS; c++) s += expf(v[c] - mx);
    float ls = logf(s) + mx;
    #pragma unroll
    for (int c = 0; c < NCLS; c++) out[n * NCLS + c] = v[c] - ls;
}

// ---------------- launch -----------------------------------------------------------
extern "C" void kernel_launch(void* const* d_in, const int* in_sizes, int n_in,
                              void* d_out, int out_size) {
    const float* x     = (const float*)d_in[0];
    const void*  ei    =               d_in[1];
    const float* ea    = (const float*)d_in[2];
    const float* W1    = (const float*)d_in[3];
    const float* root1 = (const float*)d_in[4];
    const float* bias1 = (const float*)d_in[5];
    const float* W2    = (const float*)d_in[6];
    const float* root2 = (const float*)d_in[7];
    const float* bias2 = (const float*)d_in[8];
    float* out = (float*)d_out;

    int N = in_sizes[0] / FIN;     // 50000
    int E = in_sizes[2];           // 1600000

    k_detect<<<1, 32>>>(ei);
    k_zero<<<(N * (HID + NCLS + 1) + 255) / 256, 256>>>(N);
    k_pack<<<(E + 255) / 256, 256>>>(ei, ea, E);
    k_xw1<<<592, 256>>>(x, W1, root1, bias1, N);
    long long th1 = (long long)E * 8;
    k_edge1<<<(int)((th1 + 255) / 256), 256>>>(E);
    k_h<<<(N * HID + 255) / 256, 256>>>(N);
    k_prep2<<<1184, 64>>>(W2, root2, bias2, N);
    int warps2 = (E + 5) / 6;
    k_edge2<<<(warps2 + 7) / 8, 256>>>(E);
    k_out<<<(N + 255) / 256, 256>>>(out, N);
}

// round 9
// speedup vs baseline: 2.8415x; 1.0016x over previous
#include <cuda_runtime.h>
#include <cuda_fp16.h>
#include <cstdint>

#define MAXN 50000
#define MAXE 1600000
#define FIN  48
#define HID  32
#define NCLS 10
#define KS   4
#define NB   16

// ---------------- scratch (device globals) --------------------------------------
__device__ __half    g_xw1h[MAXN * KS * HID];   // [N][4][32] fp16
__device__ float     g_rb1 [MAXN * HID];        // x@root1 + bias1 (fp32)
__device__ __half    g_xw2h[MAXN * KS * NCLS];  // [N][4][10] fp16
__device__ float     g_rb2 [MAXN * NCLS];
__device__ float     g_agg1[MAXN * HID];
__device__ float     g_agg2[MAXN * NCLS];
__device__ float     g_h   [MAXN * HID];
__device__ float     g_deg [MAXN];
__device__ uint2     g_pack[MAXE];              // x: src|dst<<16,  y: frac-bits|k0
__device__ int       g_is64;

// ---------------- helpers ---------------------------------------------------------
__device__ __forceinline__ void red_add_v4(float* addr, float4 v) {
    asm volatile("red.global.add.v4.f32 [%0], {%1,%2,%3,%4};"
                 :: "l"(addr), "f"(v.x), "f"(v.y), "f"(v.z), "f"(v.w) : "memory");
}
__device__ __forceinline__ void red_add_v2(float* addr, float2 v) {
    asm volatile("red.global.add.v2.f32 [%0], {%1,%2};"
                 :: "l"(addr), "f"(v.x), "f"(v.y) : "memory");
}
__device__ __forceinline__ unsigned long long pack2(float w) {
    unsigned long long r;
    asm("mov.b64 %0, {%1, %1};" : "=l"(r) : "f"(w));
    return r;
}
__device__ __forceinline__ void ffma2(unsigned long long& d, unsigned long long a,
                                      unsigned long long b) {
    asm("fma.rn.f32x2 %0, %1, %2, %0;" : "+l"(d) : "l"(a), "l"(b));
}
__device__ __forceinline__ float2 unpack2(unsigned long long v) {
    float lo, hi;
    asm("mov.b64 {%0, %1}, %2;" : "=f"(lo), "=f"(hi) : "l"(v));
    return make_float2(lo, hi);
}

// ---------------- dtype detection -------------------------------------------------
__global__ void k_detect(const void* __restrict__ ei) {
    int i = threadIdx.x;
    int hi = ((const int*)ei)[2 * i + 1];
    unsigned b = __ballot_sync(0xffffffffu, hi != 0);
    if (i == 0) g_is64 = (b == 0) ? 1 : 0;
}

// ---------------- zero agg1, agg2, deg --------------------------------------------
__global__ void k_zero(int N) {
    int tot = N * (HID + NCLS + 1);
    for (int i = blockIdx.x * blockDim.x + threadIdx.x; i < tot; i += gridDim.x * blockDim.x) {
        if (i < N * HID)               g_agg1[i] = 0.f;
        else if (i < N * (HID + NCLS)) g_agg2[i - N * HID] = 0.f;
        else                           g_deg[i - N * (HID + NCLS)] = 0.f;
    }
}

// ---------------- pack edges: decode once, also accumulate degree ------------------
__global__ void __launch_bounds__(256) k_pack(const void* __restrict__ ei,
                                              const float* __restrict__ ea, int E) {
    int e = blockIdx.x * blockDim.x + threadIdx.x;
    if (e >= E) return;
    int src, dst;
    if (g_is64) {
        src = (int)((const long long*)ei)[e];
        dst = (int)((const long long*)ei)[(long long)E + e];
    } else {
        src = ((const int*)ei)[e];
        dst = ((const int*)ei)[E + e];
    }
    float u = ea[e];
    float vv = u * (float)(KS - 1);
    float vf = floorf(vv);
    float frac = vv - vf;
    int k0 = min(max((int)vf, 0), KS - 1);
    g_pack[e] = make_uint2((unsigned)src | ((unsigned)dst << 16),
                           (__float_as_uint(frac) & ~3u) | (unsigned)k0);
    atomicAdd(&g_deg[dst], 1.0f);
}

// ---------------- layer-1 node GEMM: f32x2, 2 nodes/thread, W+x in smem -----------
// warp w -> cols [20w, 20w+20); lane -> nodes (lane, lane+32) of a 64-node tile.
__global__ void __launch_bounds__(256) k_xw1(const float* __restrict__ x,
                                             const float* __restrict__ W1,
                                             const float* __restrict__ root1,
                                             const float* __restrict__ bias1, int N) {
    __shared__ __align__(16) float Ws[FIN * 160];   // 30720 B
    __shared__ float xs[64 * 49];                   // 12544 B, padded stride 49
    int tile = blockIdx.x;
    // fill W (every block) and x tile, one sync
    for (int i = threadIdx.x; i < FIN * 160; i += 256) {
        int f = i / 160, j = i % 160;
        Ws[i] = (j < 128) ? W1[(((j >> 5) * FIN) + f) * HID + (j & 31)]
                          : root1[f * HID + (j - 128)];
    }
    long long base = (long long)tile * 64 * FIN;
    long long lim  = (long long)N * FIN;
    for (int idx = threadIdx.x; idx < 64 * FIN; idx += 256) {
        int nn = idx / FIN, f = idx % FIN;
        long long gi = base + idx;
        xs[nn * 49 + f] = (gi < lim) ? x[gi] : 0.f;
    }
    __syncthreads();

    const int warp = threadIdx.x >> 5;
    const int lane = threadIdx.x & 31;
    const int col0 = warp * 20;
    unsigned long long acc0[10], acc1[10];
    #pragma unroll
    for (int i = 0; i < 10; i++) { acc0[i] = 0ull; acc1[i] = 0ull; }
    const float* xrow0 = &xs[lane * 49];
    const float* xrow1 = &xs[(lane + 32) * 49];
    #pragma unroll
    for (int f = 0; f < FIN; f++) {
        unsigned long long xd0 = pack2(xrow0[f]);
        unsigned long long xd1 = pack2(xrow1[f]);
        const ulonglong2* wrow = (const ulonglong2*)&Ws[f * 160 + col0];
        #pragma unroll
        for (int c = 0; c < 5; c++) {
            ulonglong2 wv = wrow[c];
            ffma2(acc0[2*c],     wv.x, xd0);
            ffma2(acc0[2*c + 1], wv.y, xd0);
            ffma2(acc1[2*c],     wv.x, xd1);
            ffma2(acc1[2*c + 1], wv.y, xd1);
        }
    }
    #pragma unroll
    for (int half = 0; half < 2; half++) {
        int n = tile * 64 + lane + half * 32;
        if (n >= N) continue;
        const unsigned long long* acc = half ? acc1 : acc0;
        #pragma unroll
        for (int i = 0; i < 10; i++) {
            int col = col0 + 2 * i;
            float2 v = unpack2(acc[i]);
            if (col < 128) {
                *(__half2*)&g_xw1h[n * 128 + col] = __floats2half2_rn(v.x, v.y);
            } else {
                int o = col - 128;
                float2 b = *(const float2*)&bias1[o];
                *(float2*)&g_rb1[n * HID + o] = make_float2(v.x + b.x, v.y + b.y);
            }
        }
    }
}

// ---------------- layer-1 edge scatter: 8 lanes/edge, fp16 gather, fp32 red -------
__global__ void __launch_bounds__(256) k_edge1(int E) {
    long long t = (long long)blockIdx.x * blockDim.x + threadIdx.x;
    long long e = t >> 3;
    int f4 = (int)(t & 7);
    if (e >= E) return;
    uint2 r = g_pack[e];
    int src = r.x & 0xffff;
    int dst = r.x >> 16;
    int k0  = r.y & 3;
    int k1  = min(k0 + 1, KS - 1);
    float f = __uint_as_float(r.y & ~3u);
    const __half* base = g_xw1h + src * 128;
    uint2 pa = *(const uint2*)(base + k0 * 32 + f4 * 4);
    uint2 pb = *(const uint2*)(base + k1 * 32 + f4 * 4);
    float2 A0 = __half22float2(*(const __half2*)&pa.x);
    float2 A1 = __half22float2(*(const __half2*)&pa.y);
    float2 B0 = __half22float2(*(const __half2*)&pb.x);
    float2 B1 = __half22float2(*(const __half2*)&pb.y);
    float w0 = 1.0f - f;
    float4 m = make_float4(w0 * A0.x + f * B0.x, w0 * A0.y + f * B0.y,
                           w0 * A1.x + f * B1.x, w0 * A1.y + f * B1.y);
    red_add_v4(&g_agg1[dst * HID + f4 * 4], m);
}

// ---------------- layer-1 epilogue: h = elu(agg1/deg + rb1) ------------------------
__global__ void k_h(int N) {
    int i = blockIdx.x * blockDim.x + threadIdx.x;
    if (i >= N * HID) return;
    int n = i >> 5;
    float d = fmaxf(g_deg[n], 1.0f);
    float v = g_agg1[i] / d + g_rb1[i];
    g_h[i] = (v > 0.f) ? v : expm1f(v);
}

// ---------------- layer-2 node GEMM (f32x2, warp-per-column) -----------------------
__global__ void __launch_bounds__(64) k_prep2(const float* __restrict__ W2,
                                              const float* __restrict__ root2,
                                              const float* __restrict__ bias2, int N) {
    const int j = threadIdx.x;          // active j<50
    bool active = (j < 50);
    float wcol[HID];
    float binit = 0.f;
    if (j < 40) {
        int k = j / NCLS, c = j % NCLS;
        #pragma unroll
        for (int o = 0; o < HID; o++) wcol[o] = W2[(k * HID + o) * NCLS + c];
    } else if (j < 50) {
        int c = j - 40;
        #pragma unroll
        for (int o = 0; o < HID; o++) wcol[o] = root2[o * NCLS + c];
        binit = bias2[c];
    }
    __shared__ __align__(16) float hs[HID * NB];
    int ntiles = (N + NB - 1) / NB;
    for (int tile = blockIdx.x; tile < ntiles; tile += gridDim.x) {
        int n0 = tile * NB;
        __syncthreads();
        for (int idx = j; idx < HID * NB; idx += 64) {
            int nn = idx / HID, o = idx % HID;
            int n = n0 + nn;
            hs[o * NB + nn] = (n < N) ? g_h[n * HID + o] : 0.f;
        }
        __syncthreads();
        if (active) {
            unsigned long long acc2[NB / 2];
            unsigned long long binit2 = pack2(binit);
            #pragma unroll
            for (int p = 0; p < NB / 2; p++) acc2[p] = binit2;
            #pragma unroll
            for (int o = 0; o < HID; o++) {
                unsigned long long w2 = pack2(wcol[o]);
                #pragma unroll
                for (int q = 0; q < NB / 4; q++) {
                    ulonglong2 hv = *(const ulonglong2*)&hs[o * NB + q * 4];
                    ffma2(acc2[q * 2],     hv.x, w2);
                    ffma2(acc2[q * 2 + 1], hv.y, w2);
                }
            }
            #pragma unroll
            for (int p = 0; p < NB / 2; p++) {
                float2 v = unpack2(acc2[p]);
                int na = n0 + p * 2, nb2 = na + 1;
                if (na < N) {
                    if (j < 40) g_xw2h[na * 40 + j]         = __float2half(v.x);
                    else        g_rb2[na * NCLS + (j - 40)] = v.x;
                }
                if (nb2 < N) {
                    if (j < 40) g_xw2h[nb2 * 40 + j]         = __float2half(v.y);
                    else        g_rb2[nb2 * NCLS + (j - 40)] = v.y;
                }
            }
        }
    }
}

// ---------------- layer-2 edge scatter: 6 edges/warp x 5 lanes (float2) -----------
__global__ void __launch_bounds__(256) k_edge2(int E) {
    int t = blockIdx.x * blockDim.x + threadIdx.x;
    int lane = t & 31;
    int wid = t >> 5;
    int eg = lane / 5;
    int j  = lane - eg * 5;
    if (eg >= 6) return;
    long long e = (long long)wid * 6 + eg;
    if (e >= E) return;
    uint2 r = g_pack[e];
    int src = r.x & 0xffff;
    int dst = r.x >> 16;
    int k0  = r.y & 3;
    int k1  = min(k0 + 1, KS - 1);
    float f = __uint_as_float(r.y & ~3u);
    const __half* base = g_xw2h + src * 40;
    unsigned pa = *(const unsigned*)(base + k0 * 10 + j * 2);
    unsigned pb = *(const unsigned*)(base + k1 * 10 + j * 2);
    float2 A = __half22float2(*(const __half2*)&pa);
    float2 B = __half22float2(*(const __half2*)&pb);
    float w0 = 1.0f - f;
    float2 m = make_float2(w0 * A.x + f * B.x, w0 * A.y + f * B.y);
    red_add_v2(&g_agg2[dst * NCLS + j * 2], m);
}

// ---------------- final: mean + root + bias + log_softmax -------------------------
__global__ void k_out(float* __restrict__ out, int N) {
    int n = blockIdx.x * blockDim.x + threadIdx.x;
    if (n >= N) return;
    float inv = 1.0f / fmaxf(g_deg[n], 1.0f);
    float v[NCLS];
    float mx = -1e30f;
    #pragma unroll
    for (int c = 0; c < NCLS; c++) {
        v[c] = g_agg2[n * NCLS + c] * inv + g_rb2[n * NCLS + c];
        mx = fmaxf(mx, v[c]);
    }
    float s = 0.f;
    #pragma unroll
    for (int c = 0; c < NCLS; c++) s += expf(v[c] - mx);
    float ls = logf(s) + mx;
    #pragma unroll
    for (int c = 0; c < NCLS; c++) out[n * NCLS + c] = v[c] - ls;
}

// ---------------- launch -----------------------------------------------------------
extern "C" void kernel_launch(void* const* d_in, const int* in_sizes, int n_in,
                              void* d_out, int out_size) {
    const float* x     = (const float*)d_in[0];
    const void*  ei    =               d_in[1];
    const float* ea    = (const float*)d_in[2];
    const float* W1    = (const float*)d_in[3];
    const float* root1 = (const float*)d_in[4];
    const float* bias1 = (const float*)d_in[5];
    const float* W2    = (const float*)d_in[6];
    const float* root2 = (const float*)d_in[7];
    const float* bias2 = (const float*)d_in[8];
    float* out = (float*)d_out;

    int N = in_sizes[0] / FIN;     // 50000
    int E = in_sizes[2];           // 1600000

    k_detect<<<1, 32>>>(ei);
    k_zero<<<(N * (HID + NCLS + 1) + 255) / 256, 256>>>(N);
    k_pack<<<(E + 255) / 256, 256>>>(ei, ea, E);
    int ntiles1 = (N + 63) / 64;
    k_xw1<<<ntiles1, 256>>>(x, W1, root1, bias1, N);
    long long th1 = (long long)E * 8;
    k_edge1<<<(int)((th1 + 255) / 256), 256>>>(E);
    k_h<<<(N * HID + 255) / 256, 256>>>(N);
    k_prep2<<<1184, 64>>>(W2, root2, bias2, N);
    int warps2 = (E + 5) / 6;
    k_edge2<<<(warps2 + 7) / 8, 256>>>(E);
    k_out<<<(N + 255) / 256, 256>>>(out, N);
}

// round 10
// speedup vs baseline: 3.3019x; 1.1620x over previous
#include <cuda_runtime.h>
#include <cuda_fp16.h>
#include <cstdint>

#define MAXN 50000
#define MAXE 1600000
#define FIN  48
#define HID  32
#define NCLS 10
#define KS   4
#define NB   16

// ---------------- scratch (device globals) --------------------------------------
__device__ __half    g_xw1h[MAXN * KS * HID];   // [N][4][32] fp16
__device__ float     g_rb1 [MAXN * HID];        // x@root1 + bias1 (fp32)
__device__ __half    g_xw2h[MAXN * KS * NCLS];  // [N][4][10] fp16
__device__ float     g_rb2 [MAXN * NCLS];
__device__ float     g_agg1[MAXN * HID];
__device__ float     g_agg2[MAXN * NCLS];
__device__ float     g_h   [MAXN * HID];
__device__ float     g_deg [MAXN];
__device__ uint2     g_pack[MAXE];              // x: src|dst<<16,  y: frac-bits|k0
__device__ int       g_is64;

// ---------------- helpers ---------------------------------------------------------
__device__ __forceinline__ void red_add_v4(float* addr, float4 v) {
    asm volatile("red.global.add.v4.f32 [%0], {%1,%2,%3,%4};"
                 :: "l"(addr), "f"(v.x), "f"(v.y), "f"(v.z), "f"(v.w) : "memory");
}
__device__ __forceinline__ void red_add_v2(float* addr, float2 v) {
    asm volatile("red.global.add.v2.f32 [%0], {%1,%2};"
                 :: "l"(addr), "f"(v.x), "f"(v.y) : "memory");
}
__device__ __forceinline__ unsigned long long pack2(float w) {
    unsigned long long r;
    asm("mov.b64 %0, {%1, %1};" : "=l"(r) : "f"(w));
    return r;
}
__device__ __forceinline__ void ffma2(unsigned long long& d, unsigned long long a,
                                      unsigned long long b) {
    asm("fma.rn.f32x2 %0, %1, %2, %0;" : "+l"(d) : "l"(a), "l"(b));
}
__device__ __forceinline__ float2 unpack2(unsigned long long v) {
    float lo, hi;
    asm("mov.b64 {%0, %1}, %2;" : "=f"(lo), "=f"(hi) : "l"(v));
    return make_float2(lo, hi);
}
__device__ __forceinline__ void mma16816(float* d, const unsigned* a,
                                         unsigned b0, unsigned b1) {
    asm("mma.sync.aligned.m16n8k16.row.col.f32.f16.f16.f32 "
        "{%0,%1,%2,%3}, {%4,%5,%6,%7}, {%8,%9}, {%0,%1,%2,%3};"
        : "+f"(d[0]), "+f"(d[1]), "+f"(d[2]), "+f"(d[3])
        : "r"(a[0]), "r"(a[1]), "r"(a[2]), "r"(a[3]), "r"(b0), "r"(b1));
}

// ---------------- dtype detection -------------------------------------------------
__global__ void k_detect(const void* __restrict__ ei) {
    int i = threadIdx.x;
    int hi = ((const int*)ei)[2 * i + 1];
    unsigned b = __ballot_sync(0xffffffffu, hi != 0);
    if (i == 0) g_is64 = (b == 0) ? 1 : 0;
}

// ---------------- zero agg1, agg2, deg --------------------------------------------
__global__ void k_zero(int N) {
    int tot = N * (HID + NCLS + 1);
    for (int i = blockIdx.x * blockDim.x + threadIdx.x; i < tot; i += gridDim.x * blockDim.x) {
        if (i < N * HID)               g_agg1[i] = 0.f;
        else if (i < N * (HID + NCLS)) g_agg2[i - N * HID] = 0.f;
        else                           g_deg[i - N * (HID + NCLS)] = 0.f;
    }
}

// ---------------- pack edges: decode once, also accumulate degree ------------------
__global__ void __launch_bounds__(256) k_pack(const void* __restrict__ ei,
                                              const float* __restrict__ ea, int E) {
    int e = blockIdx.x * blockDim.x + threadIdx.x;
    if (e >= E) return;
    int src, dst;
    if (g_is64) {
        src = (int)((const long long*)ei)[e];
        dst = (int)((const long long*)ei)[(long long)E + e];
    } else {
        src = ((const int*)ei)[e];
        dst = ((const int*)ei)[E + e];
    }
    float u = ea[e];
    float vv = u * (float)(KS - 1);
    float vf = floorf(vv);
    float frac = vv - vf;
    int k0 = min(max((int)vf, 0), KS - 1);
    g_pack[e] = make_uint2((unsigned)src | ((unsigned)dst << 16),
                           (__float_as_uint(frac) & ~3u) | (unsigned)k0);
    atomicAdd(&g_deg[dst], 1.0f);
}

// ---------------- layer-1 node GEMM on TENSOR CORES (m16n8k16 HMMA) ----------------
// Block = 128 nodes, 8 warps; warp = 16 nodes x 160 cols (20 n-tiles, 3 k-chunks).
// xs: [128][56] fp16 (stride-56 halfs: conflict-free), wt: W^T [160][56] fp16.
__global__ void __launch_bounds__(256) k_xw1(const float* __restrict__ x,
                                             const float* __restrict__ W1,
                                             const float* __restrict__ root1,
                                             const float* __restrict__ bias1, int N) {
    __shared__ __align__(16) __half xs[128 * 56];   // 14336 B
    __shared__ __align__(16) __half wt[160 * 56];   // 17920 B
    __shared__ float bsh[HID];
    const int tid = threadIdx.x;
    // fill W^T (k-major rows of cols): wt[j][f]
    for (int i = tid; i < 160 * FIN; i += 256) {
        int j = i / FIN, f = i % FIN;
        float v = (j < 128) ? W1[(((j >> 5) * FIN) + f) * HID + (j & 31)]
                            : root1[f * HID + (j - 128)];
        wt[j * 56 + f] = __float2half(v);
    }
    if (tid < HID) bsh[tid] = bias1[tid];
    // fill x tile (convert fp32 -> fp16), zero-pad OOB nodes
    int nbase = blockIdx.x * 128;
    for (int i = tid; i < 128 * (FIN / 2); i += 256) {
        int nn = i / (FIN / 2), fp = i % (FIN / 2);
        int n = nbase + nn;
        float2 v = (n < N) ? *(const float2*)&x[(long long)n * FIN + fp * 2]
                           : make_float2(0.f, 0.f);
        *(__half2*)&xs[nn * 56 + fp * 2] = __floats2half2_rn(v.x, v.y);
    }
    __syncthreads();

    const int warp = tid >> 5;
    const int lane = tid & 31;
    const int g = lane >> 2;       // row group / n within tile
    const int t = lane & 3;        // k/col pair selector
    const int wn = warp * 16;      // warp's node offset within tile

    // A fragments for all 3 k-chunks (row-major x)
    unsigned a[3][4];
    #pragma unroll
    for (int kc = 0; kc < 3; kc++) {
        int k0 = kc * 16;
        a[kc][0] = *(const unsigned*)&xs[(wn + g)     * 56 + k0 + 2 * t];
        a[kc][1] = *(const unsigned*)&xs[(wn + g + 8) * 56 + k0 + 2 * t];
        a[kc][2] = *(const unsigned*)&xs[(wn + g)     * 56 + k0 + 2 * t + 8];
        a[kc][3] = *(const unsigned*)&xs[(wn + g + 8) * 56 + k0 + 2 * t + 8];
    }
    int node0 = nbase + wn + g;
    int node1 = node0 + 8;
    #pragma unroll
    for (int nt = 0; nt < 20; nt++) {
        int n0 = nt * 8;
        float d[4] = {0.f, 0.f, 0.f, 0.f};
        #pragma unroll
        for (int kc = 0; kc < 3; kc++) {
            unsigned b0 = *(const unsigned*)&wt[(n0 + g) * 56 + kc * 16 + 2 * t];
            unsigned b1 = *(const unsigned*)&wt[(n0 + g) * 56 + kc * 16 + 2 * t + 8];
            mma16816(d, a[kc], b0, b1);
        }
        int col = n0 + 2 * t;
        if (col < 128) {
            if (node0 < N) *(__half2*)&g_xw1h[node0 * 128 + col] = __floats2half2_rn(d[0], d[1]);
            if (node1 < N) *(__half2*)&g_xw1h[node1 * 128 + col] = __floats2half2_rn(d[2], d[3]);
        } else {
            int o = col - 128;
            float b0f = bsh[o], b1f = bsh[o + 1];
            if (node0 < N) *(float2*)&g_rb1[node0 * HID + o] = make_float2(d[0] + b0f, d[1] + b1f);
            if (node1 < N) *(float2*)&g_rb1[node1 * HID + o] = make_float2(d[2] + b0f, d[3] + b1f);
        }
    }
}

// ---------------- layer-1 edge scatter: 8 lanes/edge, fp16 gather, fp32 red -------
__global__ void __launch_bounds__(256) k_edge1(int E) {
    long long t = (long long)blockIdx.x * blockDim.x + threadIdx.x;
    long long e = t >> 3;
    int f4 = (int)(t & 7);
    if (e >= E) return;
    uint2 r = g_pack[e];
    int src = r.x & 0xffff;
    int dst = r.x >> 16;
    int k0  = r.y & 3;
    int k1  = min(k0 + 1, KS - 1);
    float f = __uint_as_float(r.y & ~3u);
    const __half* base = g_xw1h + src * 128;
    uint2 pa = *(const uint2*)(base + k0 * 32 + f4 * 4);
    uint2 pb = *(const uint2*)(base + k1 * 32 + f4 * 4);
    float2 A0 = __half22float2(*(const __half2*)&pa.x);
    float2 A1 = __half22float2(*(const __half2*)&pa.y);
    float2 B0 = __half22float2(*(const __half2*)&pb.x);
    float2 B1 = __half22float2(*(const __half2*)&pb.y);
    float w0 = 1.0f - f;
    float4 m = make_float4(w0 * A0.x + f * B0.x, w0 * A0.y + f * B0.y,
                           w0 * A1.x + f * B1.x, w0 * A1.y + f * B1.y);
    red_add_v4(&g_agg1[dst * HID + f4 * 4], m);
}

// ---------------- layer-1 epilogue: h = elu(agg1/deg + rb1) ------------------------
__global__ void k_h(int N) {
    int i = blockIdx.x * blockDim.x + threadIdx.x;
    if (i >= N * HID) return;
    int n = i >> 5;
    float d = fmaxf(g_deg[n], 1.0f);
    float v = g_agg1[i] / d + g_rb1[i];
    g_h[i] = (v > 0.f) ? v : expm1f(v);
}

// ---------------- layer-2 node GEMM (f32x2, warp-per-column) -----------------------
__global__ void __launch_bounds__(64) k_prep2(const float* __restrict__ W2,
                                              const float* __restrict__ root2,
                                              const float* __restrict__ bias2, int N) {
    const int j = threadIdx.x;          // active j<50
    bool active = (j < 50);
    float wcol[HID];
    float binit = 0.f;
    if (j < 40) {
        int k = j / NCLS, c = j % NCLS;
        #pragma unroll
        for (int o = 0; o < HID; o++) wcol[o] = W2[(k * HID + o) * NCLS + c];
    } else if (j < 50) {
        int c = j - 40;
        #pragma unroll
        for (int o = 0; o < HID; o++) wcol[o] = root2[o * NCLS + c];
        binit = bias2[c];
    }
    __shared__ __align__(16) float hs[HID * NB];
    int ntiles = (N + NB - 1) / NB;
    for (int tile = blockIdx.x; tile < ntiles; tile += gridDim.x) {
        int n0 = tile * NB;
        __syncthreads();
        for (int idx = j; idx < HID * NB; idx += 64) {
            int nn = idx / HID, o = idx % HID;
            int n = n0 + nn;
            hs[o * NB + nn] = (n < N) ? g_h[n * HID + o] : 0.f;
        }
        __syncthreads();
        if (active) {
            unsigned long long acc2[NB / 2];
            unsigned long long binit2 = pack2(binit);
            #pragma unroll
            for (int p = 0; p < NB / 2; p++) acc2[p] = binit2;
            #pragma unroll
            for (int o = 0; o < HID; o++) {
                unsigned long long w2 = pack2(wcol[o]);
                #pragma unroll
                for (int q = 0; q < NB / 4; q++) {
                    ulonglong2 hv = *(const ulonglong2*)&hs[o * NB + q * 4];
                    ffma2(acc2[q * 2],     hv.x, w2);
                    ffma2(acc2[q * 2 + 1], hv.y, w2);
                }
            }
            #pragma unroll
            for (int p = 0; p < NB / 2; p++) {
                float2 v = unpack2(acc2[p]);
                int na = n0 + p * 2, nb2 = na + 1;
                if (na < N) {
                    if (j < 40) g_xw2h[na * 40 + j]         = __float2half(v.x);
                    else        g_rb2[na * NCLS + (j - 40)] = v.x;
                }
                if (nb2 < N) {
                    if (j < 40) g_xw2h[nb2 * 40 + j]         = __float2half(v.y);
                    else        g_rb2[nb2 * NCLS + (j - 40)] = v.y;
                }
            }
        }
    }
}

// ---------------- layer-2 edge scatter: 6 edges/warp x 5 lanes (float2) -----------
__global__ void __launch_bounds__(256) k_edge2(int E) {
    int t = blockIdx.x * blockDim.x + threadIdx.x;
    int lane = t & 31;
    int wid = t >> 5;
    int eg = lane / 5;
    int j  = lane - eg * 5;
    if (eg >= 6) return;
    long long e = (long long)wid * 6 + eg;
    if (e >= E) return;
    uint2 r = g_pack[e];
    int src = r.x & 0xffff;
    int dst = r.x >> 16;
    int k0  = r.y & 3;
    int k1  = min(k0 + 1, KS - 1);
    float f = __uint_as_float(r.y & ~3u);
    const __half* base = g_xw2h + src * 40;
    unsigned pa = *(const unsigned*)(base + k0 * 10 + j * 2);
    unsigned pb = *(const unsigned*)(base + k1 * 10 + j * 2);
    float2 A = __half22float2(*(const __half2*)&pa);
    float2 B = __half22float2(*(const __half2*)&pb);
    float w0 = 1.0f - f;
    float2 m = make_float2(w0 * A.x + f * B.x, w0 * A.y + f * B.y);
    red_add_v2(&g_agg2[dst * NCLS + j * 2], m);
}

// ---------------- final: mean + root + bias + log_softmax -------------------------
__global__ void k_out(float* __restrict__ out, int N) {
    int n = blockIdx.x * blockDim.x + threadIdx.x;
    if (n >= N) return;
    float inv = 1.0f / fmaxf(g_deg[n], 1.0f);
    float v[NCLS];
    float mx = -1e30f;
    #pragma unroll
    for (int c = 0; c < NCLS; c++) {
        v[c] = g_agg2[n * NCLS + c] * inv + g_rb2[n * NCLS + c];
        mx = fmaxf(mx, v[c]);
    }
    float s = 0.f;
    #pragma unroll
    for (int c = 0; c < NCLS; c++) s += expf(v[c] - mx);
    float ls = logf(s) + mx;
    #pragma unroll
    for (int c = 0; c < NCLS; c++) out[n * NCLS + c] = v[c] - ls;
}

// ---------------- launch -----------------------------------------------------------
extern "C" void kernel_launch(void* const* d_in, const int* in_sizes, int n_in,
                              void* d_out, int out_size) {
    const float* x     = (const float*)d_in[0];
    const void*  ei    =               d_in[1];
    const float* ea    = (const float*)d_in[2];
    const float* W1    = (const float*)d_in[3];
    const float* root1 = (const float*)d_in[4];
    const float* bias1 = (const float*)d_in[5];
    const float* W2    = (const float*)d_in[6];
    const float* root2 = (const float*)d_in[7];
    const float* bias2 = (const float*)d_in[8];
    float* out = (float*)d_out;

    int N = in_sizes[0] / FIN;     // 50000
    int E = in_sizes[2];           // 1600000

    k_detect<<<1, 32>>>(ei);
    k_zero<<<(N * (HID + NCLS + 1) + 255) / 256, 256>>>(N);
    k_pack<<<(E + 255) / 256, 256>>>(ei, ea, E);
    k_xw1<<<(N + 127) / 128, 256>>>(x, W1, root1, bias1, N);
    long long th1 = (long long)E * 8;
    k_edge1<<<(int)((th1 + 255) / 256), 256>>>(E);
    k_h<<<(N * HID + 255) / 256, 256>>>(N);
    k_prep2<<<1184, 64>>>(W2, root2, bias2, N);
    int warps2 = (E + 5) / 6;
    k_edge2<<<(warps2 + 7) / 8, 256>>>(E);
    k_out<<<(N + 255) / 256, 256>>>(out, N);
}

// round 11
// speedup vs baseline: 3.7938x; 1.1490x over previous
#include <cuda_runtime.h>
#include <cuda_fp16.h>
#include <cstdint>

#define MAXN 50000
#define MAXE 1600000
#define FIN  48
#define HID  32
#define NCLS 10
#define KS   4

// ---------------- scratch (device globals) --------------------------------------
__device__ __half    g_xw1h[MAXN * KS * HID];   // [N][4][32] fp16
__device__ float     g_rb1 [MAXN * HID];        // x@root1 + bias1 (fp32)
__device__ __half    g_xw2h[MAXN * KS * NCLS];  // [N][4][10] fp16
__device__ float     g_rb2 [MAXN * NCLS];
__device__ float     g_agg1[MAXN * HID];
__device__ float     g_agg2[MAXN * NCLS];
__device__ float     g_deg [MAXN];
__device__ uint2     g_pack[MAXE];              // x: src|dst<<16,  y: frac-bits|k0
__device__ __half    g_wt1h[160 * FIN];         // W1^T+root1^T fp16 [160][48]
__device__ __half    g_wt2h[56 * HID];          // W2^T+root2^T fp16 [56][32]
__device__ int       g_is64;

// ---------------- helpers ---------------------------------------------------------
__device__ __forceinline__ void red_add_v4(float* addr, float4 v) {
    asm volatile("red.global.add.v4.f32 [%0], {%1,%2,%3,%4};"
                 :: "l"(addr), "f"(v.x), "f"(v.y), "f"(v.z), "f"(v.w) : "memory");
}
__device__ __forceinline__ void red_add_v2(float* addr, float2 v) {
    asm volatile("red.global.add.v2.f32 [%0], {%1,%2};"
                 :: "l"(addr), "f"(v.x), "f"(v.y) : "memory");
}
__device__ __forceinline__ void mma16816(float* d, const unsigned* a,
                                         unsigned b0, unsigned b1) {
    asm("mma.sync.aligned.m16n8k16.row.col.f32.f16.f16.f32 "
        "{%0,%1,%2,%3}, {%4,%5,%6,%7}, {%8,%9}, {%0,%1,%2,%3};"
        : "+f"(d[0]), "+f"(d[1]), "+f"(d[2]), "+f"(d[3])
        : "r"(a[0]), "r"(a[1]), "r"(a[2]), "r"(a[3]), "r"(b0), "r"(b1));
}

// ---------------- dtype detection -------------------------------------------------
__global__ void k_detect(const void* __restrict__ ei) {
    int i = threadIdx.x;
    int hi = ((const int*)ei)[2 * i + 1];
    unsigned b = __ballot_sync(0xffffffffu, hi != 0);
    if (i == 0) g_is64 = (b == 0) ? 1 : 0;
}

// ---------------- zero agg1, agg2, deg --------------------------------------------
__global__ void k_zero(int N) {
    int tot = N * (HID + NCLS + 1);
    for (int i = blockIdx.x * blockDim.x + threadIdx.x; i < tot; i += gridDim.x * blockDim.x) {
        if (i < N * HID)               g_agg1[i] = 0.f;
        else if (i < N * (HID + NCLS)) g_agg2[i - N * HID] = 0.f;
        else                           g_deg[i - N * (HID + NCLS)] = 0.f;
    }
}

// ---------------- weight prep: fp16 transposed copies once per call ----------------
__global__ void k_wprep(const float* __restrict__ W1, const float* __restrict__ root1,
                        const float* __restrict__ W2, const float* __restrict__ root2) {
    int i = blockIdx.x * blockDim.x + threadIdx.x;
    if (i < 160 * FIN) {
        int j = i / FIN, f = i % FIN;
        float v = (j < 128) ? W1[(((j >> 5) * FIN) + f) * HID + (j & 31)]
                            : root1[f * HID + (j - 128)];
        g_wt1h[i] = __float2half(v);
    }
    if (i < 56 * HID) {
        int c = i / HID, o = i % HID;
        float v = 0.f;
        if (c < 40)      { int k = c / NCLS, cc = c % NCLS; v = W2[(k * HID + o) * NCLS + cc]; }
        else if (c < 50) v = root2[o * NCLS + (c - 40)];
        g_wt2h[i] = __float2half(v);
    }
}

// ---------------- pack edges: decode once, also accumulate degree ------------------
__global__ void __launch_bounds__(256) k_pack(const void* __restrict__ ei,
                                              const float* __restrict__ ea, int E) {
    int e = blockIdx.x * blockDim.x + threadIdx.x;
    if (e >= E) return;
    int src, dst;
    if (g_is64) {
        src = (int)((const long long*)ei)[e];
        dst = (int)((const long long*)ei)[(long long)E + e];
    } else {
        src = ((const int*)ei)[e];
        dst = ((const int*)ei)[E + e];
    }
    float u = ea[e];
    float vv = u * (float)(KS - 1);
    float vf = floorf(vv);
    float frac = vv - vf;
    int k0 = min(max((int)vf, 0), KS - 1);
    g_pack[e] = make_uint2((unsigned)src | ((unsigned)dst << 16),
                           (__float_as_uint(frac) & ~3u) | (unsigned)k0);
    atomicAdd(&g_deg[dst], 1.0f);
}

// ---------------- layer-1 node GEMM on TENSOR CORES (m16n8k16 HMMA) ----------------
__global__ void __launch_bounds__(256) k_xw1(const float* __restrict__ x,
                                             const float* __restrict__ bias1, int N) {
    __shared__ __align__(16) __half xs[128 * 56];   // 14336 B
    __shared__ __align__(16) __half wt[160 * 56];   // 17920 B
    __shared__ float bsh[HID];
    const int tid = threadIdx.x;
    // coalesced fp16 W^T fill from g_wt1h
    for (int i2 = tid; i2 < 160 * (FIN / 2); i2 += 256) {
        int j = i2 / (FIN / 2), fp = i2 % (FIN / 2);
        *(__half2*)&wt[j * 56 + fp * 2] = ((const __half2*)g_wt1h)[i2];
    }
    if (tid < HID) bsh[tid] = bias1[tid];
    // fill x tile (convert fp32 -> fp16), zero-pad OOB nodes
    int nbase = blockIdx.x * 128;
    for (int i = tid; i < 128 * (FIN / 2); i += 256) {
        int nn = i / (FIN / 2), fp = i % (FIN / 2);
        int n = nbase + nn;
        float2 v = (n < N) ? *(const float2*)&x[(long long)n * FIN + fp * 2]
                           : make_float2(0.f, 0.f);
        *(__half2*)&xs[nn * 56 + fp * 2] = __floats2half2_rn(v.x, v.y);
    }
    __syncthreads();

    const int warp = tid >> 5;
    const int lane = tid & 31;
    const int g = lane >> 2;
    const int t = lane & 3;
    const int wn = warp * 16;

    unsigned a[3][4];
    #pragma unroll
    for (int kc = 0; kc < 3; kc++) {
        int k0 = kc * 16;
        a[kc][0] = *(const unsigned*)&xs[(wn + g)     * 56 + k0 + 2 * t];
        a[kc][1] = *(const unsigned*)&xs[(wn + g + 8) * 56 + k0 + 2 * t];
        a[kc][2] = *(const unsigned*)&xs[(wn + g)     * 56 + k0 + 2 * t + 8];
        a[kc][3] = *(const unsigned*)&xs[(wn + g + 8) * 56 + k0 + 2 * t + 8];
    }
    int node0 = nbase + wn + g;
    int node1 = node0 + 8;
    #pragma unroll
    for (int nt = 0; nt < 20; nt++) {
        int n0 = nt * 8;
        float d[4] = {0.f, 0.f, 0.f, 0.f};
        #pragma unroll
        for (int kc = 0; kc < 3; kc++) {
            unsigned b0 = *(const unsigned*)&wt[(n0 + g) * 56 + kc * 16 + 2 * t];
            unsigned b1 = *(const unsigned*)&wt[(n0 + g) * 56 + kc * 16 + 2 * t + 8];
            mma16816(d, a[kc], b0, b1);
        }
        int col = n0 + 2 * t;
        if (col < 128) {
            if (node0 < N) *(__half2*)&g_xw1h[node0 * 128 + col] = __floats2half2_rn(d[0], d[1]);
            if (node1 < N) *(__half2*)&g_xw1h[node1 * 128 + col] = __floats2half2_rn(d[2], d[3]);
        } else {
            int o = col - 128;
            float b0f = bsh[o], b1f = bsh[o + 1];
            if (node0 < N) *(float2*)&g_rb1[node0 * HID + o] = make_float2(d[0] + b0f, d[1] + b1f);
            if (node1 < N) *(float2*)&g_rb1[node1 * HID + o] = make_float2(d[2] + b0f, d[3] + b1f);
        }
    }
}

// ---------------- layer-1 edge scatter: 8 lanes/edge, fp16 gather, fp32 red -------
__global__ void __launch_bounds__(256) k_edge1(int E) {
    long long t = (long long)blockIdx.x * blockDim.x + threadIdx.x;
    long long e = t >> 3;
    int f4 = (int)(t & 7);
    if (e >= E) return;
    uint2 r = g_pack[e];
    int src = r.x & 0xffff;
    int dst = r.x >> 16;
    int k0  = r.y & 3;
    int k1  = min(k0 + 1, KS - 1);
    float f = __uint_as_float(r.y & ~3u);
    const __half* base = g_xw1h + src * 128;
    uint2 pa = *(const uint2*)(base + k0 * 32 + f4 * 4);
    uint2 pb = *(const uint2*)(base + k1 * 32 + f4 * 4);
    float2 A0 = __half22float2(*(const __half2*)&pa.x);
    float2 A1 = __half22float2(*(const __half2*)&pa.y);
    float2 B0 = __half22float2(*(const __half2*)&pb.x);
    float2 B1 = __half22float2(*(const __half2*)&pb.y);
    float w0 = 1.0f - f;
    float4 m = make_float4(w0 * A0.x + f * B0.x, w0 * A0.y + f * B0.y,
                           w0 * A1.x + f * B1.x, w0 * A1.y + f * B1.y);
    red_add_v4(&g_agg1[dst * HID + f4 * 4], m);
}

// ---------------- layer-2 node GEMM on TENSOR CORES + fused ELU epilogue -----------
__global__ void __launch_bounds__(256) k_prep2(const float* __restrict__ bias2, int N) {
    __shared__ __align__(16) __half hs[128 * 40];   // 10240 B
    __shared__ __align__(16) __half wt[56 * 40];    // 4480 B
    __shared__ float bsh[NCLS];
    const int tid = threadIdx.x;
    // wt fill (coalesced half2 from g_wt2h [56][32])
    for (int i2 = tid; i2 < 56 * (HID / 2); i2 += 256) {
        int c = i2 / (HID / 2), op = i2 % (HID / 2);
        *(__half2*)&wt[c * 40 + op * 2] = ((const __half2*)g_wt2h)[i2];
    }
    if (tid < NCLS) bsh[tid] = bias2[tid];
    // h = elu(agg1/deg + rb1) computed in-block, stored fp16
    int nbase = blockIdx.x * 128;
    for (int i = tid; i < 128 * (HID / 4); i += 256) {
        int nn = i / (HID / 4), q = i % (HID / 4);
        int n = nbase + nn;
        float4 h4 = make_float4(0.f, 0.f, 0.f, 0.f);
        if (n < N) {
            float inv = 1.0f / fmaxf(g_deg[n], 1.0f);
            float4 a  = *(const float4*)&g_agg1[n * HID + q * 4];
            float4 rb = *(const float4*)&g_rb1[n * HID + q * 4];
            float v0 = a.x * inv + rb.x, v1 = a.y * inv + rb.y;
            float v2 = a.z * inv + rb.z, v3 = a.w * inv + rb.w;
            h4.x = (v0 > 0.f) ? v0 : expm1f(v0);
            h4.y = (v1 > 0.f) ? v1 : expm1f(v1);
            h4.z = (v2 > 0.f) ? v2 : expm1f(v2);
            h4.w = (v3 > 0.f) ? v3 : expm1f(v3);
        }
        *(__half2*)&hs[nn * 40 + q * 4]     = __floats2half2_rn(h4.x, h4.y);
        *(__half2*)&hs[nn * 40 + q * 4 + 2] = __floats2half2_rn(h4.z, h4.w);
    }
    __syncthreads();

    const int warp = tid >> 5;
    const int lane = tid & 31;
    const int g = lane >> 2;
    const int t = lane & 3;
    const int wn = warp * 16;

    unsigned a[2][4];
    #pragma unroll
    for (int kc = 0; kc < 2; kc++) {
        int k0 = kc * 16;
        a[kc][0] = *(const unsigned*)&hs[(wn + g)     * 40 + k0 + 2 * t];
        a[kc][1] = *(const unsigned*)&hs[(wn + g + 8) * 40 + k0 + 2 * t];
        a[kc][2] = *(const unsigned*)&hs[(wn + g)     * 40 + k0 + 2 * t + 8];
        a[kc][3] = *(const unsigned*)&hs[(wn + g + 8) * 40 + k0 + 2 * t + 8];
    }
    int node0 = nbase + wn + g;
    int node1 = node0 + 8;
    #pragma unroll
    for (int nt = 0; nt < 7; nt++) {
        int n0 = nt * 8;
        float d[4] = {0.f, 0.f, 0.f, 0.f};
        #pragma unroll
        for (int kc = 0; kc < 2; kc++) {
            unsigned b0 = *(const unsigned*)&wt[(n0 + g) * 40 + kc * 16 + 2 * t];
            unsigned b1 = *(const unsigned*)&wt[(n0 + g) * 40 + kc * 16 + 2 * t + 8];
            mma16816(d, a[kc], b0, b1);
        }
        int col = n0 + 2 * t;
        if (col < 40) {
            if (node0 < N) *(__half2*)&g_xw2h[node0 * 40 + col] = __floats2half2_rn(d[0], d[1]);
            if (node1 < N) *(__half2*)&g_xw2h[node1 * 40 + col] = __floats2half2_rn(d[2], d[3]);
        } else if (col < 50) {
            int o = col - 40;
            float b0f = bsh[o], b1f = bsh[o + 1];
            if (node0 < N) *(float2*)&g_rb2[node0 * NCLS + o] = make_float2(d[0] + b0f, d[1] + b1f);
            if (node1 < N) *(float2*)&g_rb2[node1 * NCLS + o] = make_float2(d[2] + b0f, d[3] + b1f);
        }
    }
}

// ---------------- layer-2 edge scatter: 6 edges/warp x 5 lanes (float2) -----------
__global__ void __launch_bounds__(256) k_edge2(int E) {
    int t = blockIdx.x * blockDim.x + threadIdx.x;
    int lane = t & 31;
    int wid = t >> 5;
    int eg = lane / 5;
    int j  = lane - eg * 5;
    if (eg >= 6) return;
    long long e = (long long)wid * 6 + eg;
    if (e >= E) return;
    uint2 r = g_pack[e];
    int src = r.x & 0xffff;
    int dst = r.x >> 16;
    int k0  = r.y & 3;
    int k1  = min(k0 + 1, KS - 1);
    float f = __uint_as_float(r.y & ~3u);
    const __half* base = g_xw2h + src * 40;
    unsigned pa = *(const unsigned*)(base + k0 * 10 + j * 2);
    unsigned pb = *(const unsigned*)(base + k1 * 10 + j * 2);
    float2 A = __half22float2(*(const __half2*)&pa);
    float2 B = __half22float2(*(const __half2*)&pb);
    float w0 = 1.0f - f;
    float2 m = make_float2(w0 * A.x + f * B.x, w0 * A.y + f * B.y);
    red_add_v2(&g_agg2[dst * NCLS + j * 2], m);
}

// ---------------- final: mean + root + bias + log_softmax -------------------------
__global__ void k_out(float* __restrict__ out, int N) {
    int n = blockIdx.x * blockDim.x + threadIdx.x;
    if (n >= N) return;
    float inv = 1.0f / fmaxf(g_deg[n], 1.0f);
    float v[NCLS];
    float mx = -1e30f;
    #pragma unroll
    for (int c = 0; c < NCLS; c++) {
        v[c] = g_agg2[n * NCLS + c] * inv + g_rb2[n * NCLS + c];
        mx = fmaxf(mx, v[c]);
    }
    float s = 0.f;
    #pragma unroll
    for (int c = 0; c < NCLS; c++) s += expf(v[c] - mx);
    float ls = logf(s) + mx;
    #pragma unroll
    for (int c = 0; c < NCLS; c++) out[n * NCLS + c] = v[c] - ls;
}

// ---------------- launch -----------------------------------------------------------
extern "C" void kernel_launch(void* const* d_in, const int* in_sizes, int n_in,
                              void* d_out, int out_size) {
    const float* x     = (const float*)d_in[0];
    const void*  ei    =               d_in[1];
    const float* ea    = (const float*)d_in[2];
    const float* W1    = (const float*)d_in[3];
    const float* root1 = (const float*)d_in[4];
    const float* bias1 = (const float*)d_in[5];
    const float* W2    = (const float*)d_in[6];
    const float* root2 = (const float*)d_in[7];
    const float* bias2 = (const float*)d_in[8];
    float* out = (float*)d_out;

    int N = in_sizes[0] / FIN;     // 50000
    int E = in_sizes[2];           // 1600000

    k_detect<<<1, 32>>>(ei);
    k_zero<<<(N * (HID + NCLS + 1) + 255) / 256, 256>>>(N);
    k_wprep<<<(160 * FIN + 255) / 256, 256>>>(W1, root1, W2, root2);
    k_pack<<<(E + 255) / 256, 256>>>(ei, ea, E);
    k_xw1<<<(N + 127) / 128, 256>>>(x, bias1, N);
    long long th1 = (long long)E * 8;
    k_edge1<<<(int)((th1 + 255) / 256), 256>>>(E);
    k_prep2<<<(N + 127) / 128, 256>>>(bias2, N);
    int warps2 = (E + 5) / 6;
    k_edge2<<<(warps2 + 7) / 8, 256>>>(E);
    k_out<<<(N + 255) / 256, 256>>>(out, N);
}

// round 12
// speedup vs baseline: 4.1183x; 1.0855x over previous
#include <cuda_runtime.h>
#include <cuda_fp16.h>
#include <cstdint>

#define MAXN 50000
#define MAXE 1600000
#define FIN  48
#define HID  32
#define NCLS 10
#define KS   4

// ---------------- scratch (device globals) --------------------------------------
__device__ __half    g_xw1h[MAXN * KS * HID];   // [N][4][32] fp16
__device__ float     g_rb1 [MAXN * HID];        // x@root1 + bias1 (fp32)
__device__ __half    g_xw2h[MAXN * KS * NCLS];  // [N][4][10] fp16
__device__ float     g_rb2 [MAXN * NCLS];
__device__ float     g_agg1[MAXN * HID];
__device__ float     g_agg2[MAXN * NCLS];
__device__ float     g_deg [MAXN];
__device__ uint2     g_pack[MAXE];              // x: src|dst<<16,  y: frac-bits|k0
__device__ __half    g_wt1h[160 * FIN];         // W1^T+root1^T fp16 [160][48]
__device__ __half    g_wt2h[56 * HID];          // W2^T+root2^T fp16 [56][32]
__device__ int       g_is64;

// ---------------- helpers ---------------------------------------------------------
__device__ __forceinline__ void red_add_v4(float* addr, float4 v) {
    asm volatile("red.global.add.v4.f32 [%0], {%1,%2,%3,%4};"
                 :: "l"(addr), "f"(v.x), "f"(v.y), "f"(v.z), "f"(v.w) : "memory");
}
__device__ __forceinline__ void red_add_v2(float* addr, float2 v) {
    asm volatile("red.global.add.v2.f32 [%0], {%1,%2};"
                 :: "l"(addr), "f"(v.x), "f"(v.y) : "memory");
}
__device__ __forceinline__ void mma16816(float* d, const unsigned* a,
                                         unsigned b0, unsigned b1) {
    asm("mma.sync.aligned.m16n8k16.row.col.f32.f16.f16.f32 "
        "{%0,%1,%2,%3}, {%4,%5,%6,%7}, {%8,%9}, {%0,%1,%2,%3};"
        : "+f"(d[0]), "+f"(d[1]), "+f"(d[2]), "+f"(d[3])
        : "r"(a[0]), "r"(a[1]), "r"(a[2]), "r"(a[3]), "r"(b0), "r"(b1));
}
__device__ __forceinline__ uint2 enc_edge(int src, int dst, float u) {
    float vv = u * (float)(KS - 1);
    float vf = floorf(vv);
    float frac = vv - vf;
    int k0 = min(max((int)vf, 0), KS - 1);
    return make_uint2((unsigned)src | ((unsigned)dst << 16),
                      (__float_as_uint(frac) & ~3u) | (unsigned)k0);
}

// ---------------- init: detect dtype + wprep (block 0) + zero (other blocks) ------
__global__ void k_init(const void* __restrict__ ei,
                       const float* __restrict__ W1, const float* __restrict__ root1,
                       const float* __restrict__ W2, const float* __restrict__ root2,
                       int N) {
    if (blockIdx.x == 0) {
        if (threadIdx.x < 32) {
            int hi = ((const int*)ei)[2 * threadIdx.x + 1];
            unsigned b = __ballot_sync(0xffffffffu, hi != 0);
            if (threadIdx.x == 0) g_is64 = (b == 0) ? 1 : 0;
        }
        for (int i = threadIdx.x; i < 160 * FIN; i += 256) {
            int j = i / FIN, f = i % FIN;
            float v = (j < 128) ? W1[(((j >> 5) * FIN) + f) * HID + (j & 31)]
                                : root1[f * HID + (j - 128)];
            g_wt1h[i] = __float2half(v);
        }
        for (int i = threadIdx.x; i < 56 * HID; i += 256) {
            int c = i / HID, o = i % HID;
            float v = 0.f;
            if (c < 40)      { int k = c / NCLS, cc = c % NCLS; v = W2[(k * HID + o) * NCLS + cc]; }
            else if (c < 50) v = root2[o * NCLS + (c - 40)];
            g_wt2h[i] = __float2half(v);
        }
    } else {
        int tot = N * (HID + NCLS + 1);
        for (int i = (blockIdx.x - 1) * 256 + threadIdx.x; i < tot;
             i += (gridDim.x - 1) * 256) {
            if (i < N * HID)               g_agg1[i] = 0.f;
            else if (i < N * (HID + NCLS)) g_agg2[i - N * HID] = 0.f;
            else                           g_deg[i - N * (HID + NCLS)] = 0.f;
        }
    }
}

// ---------------- fused: xw1 tensor-core GEMM (blocks < xwblocks) + edge pack -----
__global__ void __launch_bounds__(256) k_main1(const float* __restrict__ x,
                                               const float* __restrict__ bias1,
                                               const void* __restrict__ ei,
                                               const float* __restrict__ ea,
                                               int N, int E, int xwblocks) {
    __shared__ __align__(16) __half xs[128 * 56];   // 14336 B
    __shared__ __align__(16) __half wt[160 * 56];   // 17920 B
    __shared__ float bsh[HID];
    const int tid = threadIdx.x;

    if (blockIdx.x >= xwblocks) {
        // ---------------- pack: 2 edges per thread, vector loads ----------------
        int b = blockIdx.x - xwblocks;
        long long e0 = ((long long)b * 256 + tid) * 2;
        if (e0 >= E) return;
        bool vec = ((E & 1) == 0) && (e0 + 1 < E);
        if (vec) {
            int src0, dst0, src1, dst1;
            if (g_is64) {
                longlong2 s = *(const longlong2*)((const long long*)ei + e0);
                longlong2 d = *(const longlong2*)((const long long*)ei + E + e0);
                src0 = (int)s.x; src1 = (int)s.y; dst0 = (int)d.x; dst1 = (int)d.y;
            } else {
                int2 s = *(const int2*)((const int*)ei + e0);
                int2 d = *(const int2*)((const int*)ei + E + e0);
                src0 = s.x; src1 = s.y; dst0 = d.x; dst1 = d.y;
            }
            float2 u = *(const float2*)(ea + e0);
            uint2 r0 = enc_edge(src0, dst0, u.x);
            uint2 r1 = enc_edge(src1, dst1, u.y);
            *(uint4*)&g_pack[e0] = make_uint4(r0.x, r0.y, r1.x, r1.y);
            atomicAdd(&g_deg[dst0], 1.0f);
            atomicAdd(&g_deg[dst1], 1.0f);
        } else {
            for (long long e = e0; e < e0 + 2 && e < E; e++) {
                int src, dst;
                if (g_is64) {
                    src = (int)((const long long*)ei)[e];
                    dst = (int)((const long long*)ei)[E + e];
                } else {
                    src = ((const int*)ei)[e];
                    dst = ((const int*)ei)[E + e];
                }
                g_pack[e] = enc_edge(src, dst, ea[e]);
                atomicAdd(&g_deg[dst], 1.0f);
            }
        }
        return;
    }

    // ---------------- xw1: HMMA m16n8k16 ------------------------------------------
    for (int i2 = tid; i2 < 160 * (FIN / 2); i2 += 256) {
        int j = i2 / (FIN / 2), fp = i2 % (FIN / 2);
        *(__half2*)&wt[j * 56 + fp * 2] = ((const __half2*)g_wt1h)[i2];
    }
    if (tid < HID) bsh[tid] = bias1[tid];
    int nbase = blockIdx.x * 128;
    for (int i = tid; i < 128 * (FIN / 2); i += 256) {
        int nn = i / (FIN / 2), fp = i % (FIN / 2);
        int n = nbase + nn;
        float2 v = (n < N) ? *(const float2*)&x[(long long)n * FIN + fp * 2]
                           : make_float2(0.f, 0.f);
        *(__half2*)&xs[nn * 56 + fp * 2] = __floats2half2_rn(v.x, v.y);
    }
    __syncthreads();

    const int warp = tid >> 5;
    const int lane = tid & 31;
    const int g = lane >> 2;
    const int t = lane & 3;
    const int wn = warp * 16;

    unsigned a[3][4];
    #pragma unroll
    for (int kc = 0; kc < 3; kc++) {
        int k0 = kc * 16;
        a[kc][0] = *(const unsigned*)&xs[(wn + g)     * 56 + k0 + 2 * t];
        a[kc][1] = *(const unsigned*)&xs[(wn + g + 8) * 56 + k0 + 2 * t];
        a[kc][2] = *(const unsigned*)&xs[(wn + g)     * 56 + k0 + 2 * t + 8];
        a[kc][3] = *(const unsigned*)&xs[(wn + g + 8) * 56 + k0 + 2 * t + 8];
    }
    int node0 = nbase + wn + g;
    int node1 = node0 + 8;
    #pragma unroll
    for (int nt = 0; nt < 20; nt++) {
        int n0 = nt * 8;
        float d[4] = {0.f, 0.f, 0.f, 0.f};
        #pragma unroll
        for (int kc = 0; kc < 3; kc++) {
            unsigned b0 = *(const unsigned*)&wt[(n0 + g) * 56 + kc * 16 + 2 * t];
            unsigned b1 = *(const unsigned*)&wt[(n0 + g) * 56 + kc * 16 + 2 * t + 8];
            mma16816(d, a[kc], b0, b1);
        }
        int col = n0 + 2 * t;
        if (col < 128) {
            if (node0 < N) *(__half2*)&g_xw1h[node0 * 128 + col] = __floats2half2_rn(d[0], d[1]);
            if (node1 < N) *(__half2*)&g_xw1h[node1 * 128 + col] = __floats2half2_rn(d[2], d[3]);
        } else {
            int o = col - 128;
            float b0f = bsh[o], b1f = bsh[o + 1];
            if (node0 < N) *(float2*)&g_rb1[node0 * HID + o] = make_float2(d[0] + b0f, d[1] + b1f);
            if (node1 < N) *(float2*)&g_rb1[node1 * HID + o] = make_float2(d[2] + b0f, d[3] + b1f);
        }
    }
}

// ---------------- layer-1 edge scatter: 8 lanes/edge, fp16 gather, fp32 red -------
__global__ void __launch_bounds__(256) k_edge1(int E) {
    long long t = (long long)blockIdx.x * blockDim.x + threadIdx.x;
    long long e = t >> 3;
    int f4 = (int)(t & 7);
    if (e >= E) return;
    uint2 r = g_pack[e];
    int src = r.x & 0xffff;
    int dst = r.x >> 16;
    int k0  = r.y & 3;
    int k1  = min(k0 + 1, KS - 1);
    float f = __uint_as_float(r.y & ~3u);
    const __half* base = g_xw1h + src * 128;
    uint2 pa = *(const uint2*)(base + k0 * 32 + f4 * 4);
    uint2 pb = *(const uint2*)(base + k1 * 32 + f4 * 4);
    float2 A0 = __half22float2(*(const __half2*)&pa.x);
    float2 A1 = __half22float2(*(const __half2*)&pa.y);
    float2 B0 = __half22float2(*(const __half2*)&pb.x);
    float2 B1 = __half22float2(*(const __half2*)&pb.y);
    float w0 = 1.0f - f;
    float4 m = make_float4(w0 * A0.x + f * B0.x, w0 * A0.y + f * B0.y,
                           w0 * A1.x + f * B1.x, w0 * A1.y + f * B1.y);
    red_add_v4(&g_agg1[dst * HID + f4 * 4], m);
}

// ---------------- layer-2 node GEMM on TENSOR CORES + fused ELU epilogue -----------
__global__ void __launch_bounds__(256) k_prep2(const float* __restrict__ bias2, int N) {
    __shared__ __align__(16) __half hs[128 * 40];   // 10240 B
    __shared__ __align__(16) __half wt[56 * 40];    // 4480 B
    __shared__ float bsh[NCLS];
    const int tid = threadIdx.x;
    for (int i2 = tid; i2 < 56 * (HID / 2); i2 += 256) {
        int c = i2 / (HID / 2), op = i2 % (HID / 2);
        *(__half2*)&wt[c * 40 + op * 2] = ((const __half2*)g_wt2h)[i2];
    }
    if (tid < NCLS) bsh[tid] = bias2[tid];
    int nbase = blockIdx.x * 128;
    for (int i = tid; i < 128 * (HID / 4); i += 256) {
        int nn = i / (HID / 4), q = i % (HID / 4);
        int n = nbase + nn;
        float4 h4 = make_float4(0.f, 0.f, 0.f, 0.f);
        if (n < N) {
            float inv = 1.0f / fmaxf(g_deg[n], 1.0f);
            float4 a  = *(const float4*)&g_agg1[n * HID + q * 4];
            float4 rb = *(const float4*)&g_rb1[n * HID + q * 4];
            float v0 = a.x * inv + rb.x, v1 = a.y * inv + rb.y;
            float v2 = a.z * inv + rb.z, v3 = a.w * inv + rb.w;
            h4.x = (v0 > 0.f) ? v0 : expm1f(v0);
            h4.y = (v1 > 0.f) ? v1 : expm1f(v1);
            h4.z = (v2 > 0.f) ? v2 : expm1f(v2);
            h4.w = (v3 > 0.f) ? v3 : expm1f(v3);
        }
        *(__half2*)&hs[nn * 40 + q * 4]     = __floats2half2_rn(h4.x, h4.y);
        *(__half2*)&hs[nn * 40 + q * 4 + 2] = __floats2half2_rn(h4.z, h4.w);
    }
    __syncthreads();

    const int warp = tid >> 5;
    const int lane = tid & 31;
    const int g = lane >> 2;
    const int t = lane & 3;
    const int wn = warp * 16;

    unsigned a[2][4];
    #pragma unroll
    for (int kc = 0; kc < 2; kc++) {
        int k0 = kc * 16;
        a[kc][0] = *(const unsigned*)&hs[(wn + g)     * 40 + k0 + 2 * t];
        a[kc][1] = *(const unsigned*)&hs[(wn + g + 8) * 40 + k0 + 2 * t];
        a[kc][2] = *(const unsigned*)&hs[(wn + g)     * 40 + k0 + 2 * t + 8];
        a[kc][3] = *(const unsigned*)&hs[(wn + g + 8) * 40 + k0 + 2 * t + 8];
    }
    int node0 = nbase + wn + g;
    int node1 = node0 + 8;
    #pragma unroll
    for (int nt = 0; nt < 7; nt++) {
        int n0 = nt * 8;
        float d[4] = {0.f, 0.f, 0.f, 0.f};
        #pragma unroll
        for (int kc = 0; kc < 2; kc++) {
            unsigned b0 = *(const unsigned*)&wt[(n0 + g) * 40 + kc * 16 + 2 * t];
            unsigned b1 = *(const unsigned*)&wt[(n0 + g) * 40 + kc * 16 + 2 * t + 8];
            mma16816(d, a[kc], b0, b1);
        }
        int col = n0 + 2 * t;
        if (col < 40) {
            if (node0 < N) *(__half2*)&g_xw2h[node0 * 40 + col] = __floats2half2_rn(d[0], d[1]);
            if (node1 < N) *(__half2*)&g_xw2h[node1 * 40 + col] = __floats2half2_rn(d[2], d[3]);
        } else if (col < 50) {
            int o = col - 40;
            float b0f = bsh[o], b1f = bsh[o + 1];
            if (node0 < N) *(float2*)&g_rb2[node0 * NCLS + o] = make_float2(d[0] + b0f, d[1] + b1f);
            if (node1 < N) *(float2*)&g_rb2[node1 * NCLS + o] = make_float2(d[2] + b0f, d[3] + b1f);
        }
    }
}

// ---------------- layer-2 edge scatter: 6 edges/warp x 5 lanes (float2) -----------
__global__ void __launch_bounds__(256) k_edge2(int E) {
    int t = blockIdx.x * blockDim.x + threadIdx.x;
    int lane = t & 31;
    int wid = t >> 5;
    int eg = lane / 5;
    int j  = lane - eg * 5;
    if (eg >= 6) return;
    long long e = (long long)wid * 6 + eg;
    if (e >= E) return;
    uint2 r = g_pack[e];
    int src = r.x & 0xffff;
    int dst = r.x >> 16;
    int k0  = r.y & 3;
    int k1  = min(k0 + 1, KS - 1);
    float f = __uint_as_float(r.y & ~3u);
    const __half* base = g_xw2h + src * 40;
    unsigned pa = *(const unsigned*)(base + k0 * 10 + j * 2);
    unsigned pb = *(const unsigned*)(base + k1 * 10 + j * 2);
    float2 A = __half22float2(*(const __half2*)&pa);
    float2 B = __half22float2(*(const __half2*)&pb);
    float w0 = 1.0f - f;
    float2 m = make_float2(w0 * A.x + f * B.x, w0 * A.y + f * B.y);
    red_add_v2(&g_agg2[dst * NCLS + j * 2], m);
}

// ---------------- final: mean + root + bias + log_softmax -------------------------
__global__ void k_out(float* __restrict__ out, int N) {
    int n = blockIdx.x * blockDim.x + threadIdx.x;
    if (n >= N) return;
    float inv = 1.0f / fmaxf(g_deg[n], 1.0f);
    float v[NCLS];
    float mx = -1e30f;
    #pragma unroll
    for (int q = 0; q < NCLS / 2; q++) {
        float2 a  = *(const float2*)&g_agg2[n * NCLS + q * 2];
        float2 rb = *(const float2*)&g_rb2[n * NCLS + q * 2];
        v[q*2]   = a.x * inv + rb.x;
        v[q*2+1] = a.y * inv + rb.y;
        mx = fmaxf(mx, fmaxf(v[q*2], v[q*2+1]));
    }
    float s = 0.f;
    #pragma unroll
    for (int c = 0; c < NCLS; c++) s += expf(v[c] - mx);
    float ls = logf(s) + mx;
    float2* o2 = (float2*)&out[n * NCLS];
    #pragma unroll
    for (int q = 0; q < NCLS / 2; q++)
        o2[q] = make_float2(v[q*2] - ls, v[q*2+1] - ls);
}

// ---------------- launch -----------------------------------------------------------
extern "C" void kernel_launch(void* const* d_in, const int* in_sizes, int n_in,
                              void* d_out, int out_size) {
    const float* x     = (const float*)d_in[0];
    const void*  ei    =               d_in[1];
    const float* ea    = (const float*)d_in[2];
    const float* W1    = (const float*)d_in[3];
    const float* root1 = (const float*)d_in[4];
    const float* bias1 = (const float*)d_in[5];
    const float* W2    = (const float*)d_in[6];
    const float* root2 = (const float*)d_in[7];
    const float* bias2 = (const float*)d_in[8];
    float* out = (float*)d_out;

    int N = in_sizes[0] / FIN;     // 50000
    int E = in_sizes[2];           // 1600000

    int zgrid = (N * (HID + NCLS + 1) + 255) / 256 + 1;
    k_init<<<zgrid, 256>>>(ei, W1, root1, W2, root2, N);
    int xwblocks = (N + 127) / 128;
    int packblocks = (E / 2 + 256) / 256;      // 2 edges/thread (+1 for odd E)
    k_main1<<<xwblocks + packblocks, 256>>>(x, bias1, ei, ea, N, E, xwblocks);
    long long th1 = (long long)E * 8;
    k_edge1<<<(int)((th1 + 255) / 256), 256>>>(E);
    k_prep2<<<(N + 127) / 128, 256>>>(bias2, N);
    int warps2 = (E + 5) / 6;
    k_edge2<<<(warps2 + 7) / 8, 256>>>(E);
    k_out<<<(N + 255) / 256, 256>>>(out, N);
}

// round 13
// speedup vs baseline: 4.8637x; 1.1810x over previous
#include <cuda_runtime.h>
#include <cuda_fp16.h>
#include <cstdint>

#define MAXN 50000
#define MAXE 1600000
#define FIN  48
#define HID  32
#define NCLS 10
#define KS   4

// ---------------- scratch (device globals) --------------------------------------
__device__ __half    g_xw1h[MAXN * KS * HID];   // [N][4][32] fp16
__device__ float     g_rb1 [MAXN * HID];        // x@root1 + bias1 (fp32)
__device__ __half    g_xw2h[MAXN * KS * NCLS];  // [N][4][10] fp16
__device__ float     g_rb2 [MAXN * NCLS];
__device__ __align__(16) __half g_agg1h[MAXN * HID];
__device__ __align__(8)  __half g_agg2h[MAXN * NCLS];
__device__ float     g_deg [MAXN];
__device__ uint2     g_pack[MAXE];              // x: src|dst<<16,  y: frac-bits|k0
__device__ __half    g_wt1h[160 * FIN];         // W1^T+root1^T fp16 [160][48]
__device__ __half    g_wt2h[56 * HID];          // W2^T+root2^T fp16 [56][32]
__device__ int       g_is64;

// ---------------- helpers ---------------------------------------------------------
__device__ __forceinline__ void red_add_v4h2(__half* addr, uint4 v) {
    asm volatile("red.global.add.noftz.v4.f16x2 [%0], {%1,%2,%3,%4};"
                 :: "l"(addr), "r"(v.x), "r"(v.y), "r"(v.z), "r"(v.w) : "memory");
}
__device__ __forceinline__ void red_add_h2(__half* addr, unsigned v) {
    asm volatile("red.global.add.noftz.f16x2 [%0], %1;"
                 :: "l"(addr), "r"(v) : "memory");
}
__device__ __forceinline__ void mma16816(float* d, const unsigned* a,
                                         unsigned b0, unsigned b1) {
    asm("mma.sync.aligned.m16n8k16.row.col.f32.f16.f16.f32 "
        "{%0,%1,%2,%3}, {%4,%5,%6,%7}, {%8,%9}, {%0,%1,%2,%3};"
        : "+f"(d[0]), "+f"(d[1]), "+f"(d[2]), "+f"(d[3])
        : "r"(a[0]), "r"(a[1]), "r"(a[2]), "r"(a[3]), "r"(b0), "r"(b1));
}
__device__ __forceinline__ uint2 enc_edge(int src, int dst, float u) {
    float vv = u * (float)(KS - 1);
    float vf = floorf(vv);
    float frac = vv - vf;
    int k0 = min(max((int)vf, 0), KS - 1);
    return make_uint2((unsigned)src | ((unsigned)dst << 16),
                      (__float_as_uint(frac) & ~3u) | (unsigned)k0);
}

// ---------------- init: detect dtype + wprep (block 0) + zero (other blocks) ------
__global__ void k_init(const void* __restrict__ ei,
                       const float* __restrict__ W1, const float* __restrict__ root1,
                       const float* __restrict__ W2, const float* __restrict__ root2,
                       int N) {
    if (blockIdx.x == 0) {
        if (threadIdx.x < 32) {
            int hi = ((const int*)ei)[2 * threadIdx.x + 1];
            unsigned b = __ballot_sync(0xffffffffu, hi != 0);
            if (threadIdx.x == 0) g_is64 = (b == 0) ? 1 : 0;
        }
        for (int i = threadIdx.x; i < 160 * FIN; i += 256) {
            int j = i / FIN, f = i % FIN;
            float v = (j < 128) ? W1[(((j >> 5) * FIN) + f) * HID + (j & 31)]
                                : root1[f * HID + (j - 128)];
            g_wt1h[i] = __float2half(v);
        }
        for (int i = threadIdx.x; i < 56 * HID; i += 256) {
            int c = i / HID, o = i % HID;
            float v = 0.f;
            if (c < 40)      { int k = c / NCLS, cc = c % NCLS; v = W2[(k * HID + o) * NCLS + cc]; }
            else if (c < 50) v = root2[o * NCLS + (c - 40)];
            g_wt2h[i] = __float2half(v);
        }
    } else {
        // zero: agg1h (N*16 words) + agg2h (N*5 words) + deg (N words)
        int tot = N * 22;
        for (int i = (blockIdx.x - 1) * 256 + threadIdx.x; i < tot;
             i += (gridDim.x - 1) * 256) {
            if (i < N * 16)          ((unsigned*)g_agg1h)[i] = 0u;
            else if (i < N * 21)     ((unsigned*)g_agg2h)[i - N * 16] = 0u;
            else                     g_deg[i - N * 21] = 0.f;
        }
    }
}

// ---------------- fused: xw1 tensor-core GEMM (blocks < xwblocks) + edge pack -----
__global__ void __launch_bounds__(256) k_main1(const float* __restrict__ x,
                                               const float* __restrict__ bias1,
                                               const void* __restrict__ ei,
                                               const float* __restrict__ ea,
                                               int N, int E, int xwblocks) {
    __shared__ __align__(16) __half xs[128 * 56];   // 14336 B
    __shared__ __align__(16) __half wt[160 * 56];   // 17920 B
    __shared__ float bsh[HID];
    const int tid = threadIdx.x;

    if (blockIdx.x >= xwblocks) {
        int b = blockIdx.x - xwblocks;
        long long e0 = ((long long)b * 256 + tid) * 2;
        if (e0 >= E) return;
        bool vec = ((E & 1) == 0) && (e0 + 1 < E);
        if (vec) {
            int src0, dst0, src1, dst1;
            if (g_is64) {
                longlong2 s = *(const longlong2*)((const long long*)ei + e0);
                longlong2 d = *(const longlong2*)((const long long*)ei + E + e0);
                src0 = (int)s.x; src1 = (int)s.y; dst0 = (int)d.x; dst1 = (int)d.y;
            } else {
                int2 s = *(const int2*)((const int*)ei + e0);
                int2 d = *(const int2*)((const int*)ei + E + e0);
                src0 = s.x; src1 = s.y; dst0 = d.x; dst1 = d.y;
            }
            float2 u = *(const float2*)(ea + e0);
            uint2 r0 = enc_edge(src0, dst0, u.x);
            uint2 r1 = enc_edge(src1, dst1, u.y);
            *(uint4*)&g_pack[e0] = make_uint4(r0.x, r0.y, r1.x, r1.y);
            atomicAdd(&g_deg[dst0], 1.0f);
            atomicAdd(&g_deg[dst1], 1.0f);
        } else {
            for (long long e = e0; e < e0 + 2 && e < E; e++) {
                int src, dst;
                if (g_is64) {
                    src = (int)((const long long*)ei)[e];
                    dst = (int)((const long long*)ei)[E + e];
                } else {
                    src = ((const int*)ei)[e];
                    dst = ((const int*)ei)[E + e];
                }
                g_pack[e] = enc_edge(src, dst, ea[e]);
                atomicAdd(&g_deg[dst], 1.0f);
            }
        }
        return;
    }

    // xw1 HMMA
    for (int i2 = tid; i2 < 160 * (FIN / 2); i2 += 256) {
        int j = i2 / (FIN / 2), fp = i2 % (FIN / 2);
        *(__half2*)&wt[j * 56 + fp * 2] = ((const __half2*)g_wt1h)[i2];
    }
    if (tid < HID) bsh[tid] = bias1[tid];
    int nbase = blockIdx.x * 128;
    for (int i = tid; i < 128 * (FIN / 2); i += 256) {
        int nn = i / (FIN / 2), fp = i % (FIN / 2);
        int n = nbase + nn;
        float2 v = (n < N) ? *(const float2*)&x[(long long)n * FIN + fp * 2]
                           : make_float2(0.f, 0.f);
        *(__half2*)&xs[nn * 56 + fp * 2] = __floats2half2_rn(v.x, v.y);
    }
    __syncthreads();

    const int warp = tid >> 5;
    const int lane = tid & 31;
    const int g = lane >> 2;
    const int t = lane & 3;
    const int wn = warp * 16;

    unsigned a[3][4];
    #pragma unroll
    for (int kc = 0; kc < 3; kc++) {
        int k0 = kc * 16;
        a[kc][0] = *(const unsigned*)&xs[(wn + g)     * 56 + k0 + 2 * t];
        a[kc][1] = *(const unsigned*)&xs[(wn + g + 8) * 56 + k0 + 2 * t];
        a[kc][2] = *(const unsigned*)&xs[(wn + g)     * 56 + k0 + 2 * t + 8];
        a[kc][3] = *(const unsigned*)&xs[(wn + g + 8) * 56 + k0 + 2 * t + 8];
    }
    int node0 = nbase + wn + g;
    int node1 = node0 + 8;
    #pragma unroll
    for (int nt = 0; nt < 20; nt++) {
        int n0 = nt * 8;
        float d[4] = {0.f, 0.f, 0.f, 0.f};
        #pragma unroll
        for (int kc = 0; kc < 3; kc++) {
            unsigned b0 = *(const unsigned*)&wt[(n0 + g) * 56 + kc * 16 + 2 * t];
            unsigned b1 = *(const unsigned*)&wt[(n0 + g) * 56 + kc * 16 + 2 * t + 8];
            mma16816(d, a[kc], b0, b1);
        }
        int col = n0 + 2 * t;
        if (col < 128) {
            if (node0 < N) *(__half2*)&g_xw1h[node0 * 128 + col] = __floats2half2_rn(d[0], d[1]);
            if (node1 < N) *(__half2*)&g_xw1h[node1 * 128 + col] = __floats2half2_rn(d[2], d[3]);
        } else {
            int o = col - 128;
            float b0f = bsh[o], b1f = bsh[o + 1];
            if (node0 < N) *(float2*)&g_rb1[node0 * HID + o] = make_float2(d[0] + b0f, d[1] + b1f);
            if (node1 < N) *(float2*)&g_rb1[node1 * HID + o] = make_float2(d[2] + b0f, d[3] + b1f);
        }
    }
}

// ---------------- layer-1 edge scatter: 4 lanes/edge, uint4 gather, f16x2 red -----
__global__ void __launch_bounds__(256) k_edge1(int E) {
    long long t = (long long)blockIdx.x * blockDim.x + threadIdx.x;
    long long e = t >> 2;
    int j = (int)(t & 3);           // 8 features per lane
    if (e >= E) return;
    uint2 r = g_pack[e];
    int src = r.x & 0xffff;
    int dst = r.x >> 16;
    int k0  = r.y & 3;
    int k1  = min(k0 + 1, KS - 1);
    float f = __uint_as_float(r.y & ~3u);
    const __half* base = g_xw1h + src * 128;
    uint4 pa = *(const uint4*)(base + k0 * 32 + j * 8);
    uint4 pb = *(const uint4*)(base + k1 * 32 + j * 8);
    float w0 = 1.0f - f;
    uint4 o;
    #pragma unroll
    for (int q = 0; q < 4; q++) {
        float2 A = __half22float2(((const __half2*)&pa)[q]);
        float2 B = __half22float2(((const __half2*)&pb)[q]);
        __half2 h = __floats2half2_rn(w0 * A.x + f * B.x, w0 * A.y + f * B.y);
        ((__half2*)&o)[q] = h;
    }
    red_add_v4h2(g_agg1h + dst * HID + j * 8, o);
}

// ---------------- layer-2 node GEMM (64-node tiles) + fused ELU epilogue -----------
__global__ void __launch_bounds__(128) k_prep2(const float* __restrict__ bias2, int N) {
    __shared__ __align__(16) __half hs[64 * 40];    // 5120 B
    __shared__ __align__(16) __half wt[56 * 40];    // 4480 B
    __shared__ float bsh[NCLS];
    const int tid = threadIdx.x;
    for (int i2 = tid; i2 < 56 * (HID / 2); i2 += 128) {
        int c = i2 / (HID / 2), op = i2 % (HID / 2);
        *(__half2*)&wt[c * 40 + op * 2] = ((const __half2*)g_wt2h)[i2];
    }
    if (tid < NCLS) bsh[tid] = bias2[tid];
    int nbase = blockIdx.x * 64;
    for (int i = tid; i < 64 * (HID / 4); i += 128) {
        int nn = i / (HID / 4), q = i % (HID / 4);
        int n = nbase + nn;
        float4 h4 = make_float4(0.f, 0.f, 0.f, 0.f);
        if (n < N) {
            float inv = 1.0f / fmaxf(g_deg[n], 1.0f);
            uint2 ah = *(const uint2*)&g_agg1h[n * HID + q * 4];
            float2 a01 = __half22float2(*(const __half2*)&ah.x);
            float2 a23 = __half22float2(*(const __half2*)&ah.y);
            float4 rb = *(const float4*)&g_rb1[n * HID + q * 4];
            float v0 = a01.x * inv + rb.x, v1 = a01.y * inv + rb.y;
            float v2 = a23.x * inv + rb.z, v3 = a23.y * inv + rb.w;
            h4.x = (v0 > 0.f) ? v0 : expm1f(v0);
            h4.y = (v1 > 0.f) ? v1 : expm1f(v1);
            h4.z = (v2 > 0.f) ? v2 : expm1f(v2);
            h4.w = (v3 > 0.f) ? v3 : expm1f(v3);
        }
        *(__half2*)&hs[nn * 40 + q * 4]     = __floats2half2_rn(h4.x, h4.y);
        *(__half2*)&hs[nn * 40 + q * 4 + 2] = __floats2half2_rn(h4.z, h4.w);
    }
    __syncthreads();

    const int warp = tid >> 5;      // 0..3
    const int lane = tid & 31;
    const int g = lane >> 2;
    const int t = lane & 3;
    const int wn = warp * 16;

    unsigned a[2][4];
    #pragma unroll
    for (int kc = 0; kc < 2; kc++) {
        int k0 = kc * 16;
        a[kc][0] = *(const unsigned*)&hs[(wn + g)     * 40 + k0 + 2 * t];
        a[kc][1] = *(const unsigned*)&hs[(wn + g + 8) * 40 + k0 + 2 * t];
        a[kc][2] = *(const unsigned*)&hs[(wn + g)     * 40 + k0 + 2 * t + 8];
        a[kc][3] = *(const unsigned*)&hs[(wn + g + 8) * 40 + k0 + 2 * t + 8];
    }
    int node0 = nbase + wn + g;
    int node1 = node0 + 8;
    #pragma unroll
    for (int nt = 0; nt < 7; nt++) {
        int n0 = nt * 8;
        float d[4] = {0.f, 0.f, 0.f, 0.f};
        #pragma unroll
        for (int kc = 0; kc < 2; kc++) {
            unsigned b0 = *(const unsigned*)&wt[(n0 + g) * 40 + kc * 16 + 2 * t];
            unsigned b1 = *(const unsigned*)&wt[(n0 + g) * 40 + kc * 16 + 2 * t + 8];
            mma16816(d, a[kc], b0, b1);
        }
        int col = n0 + 2 * t;
        if (col < 40) {
            if (node0 < N) *(__half2*)&g_xw2h[node0 * 40 + col] = __floats2half2_rn(d[0], d[1]);
            if (node1 < N) *(__half2*)&g_xw2h[node1 * 40 + col] = __floats2half2_rn(d[2], d[3]);
        } else if (col < 50) {
            int o = col - 40;
            float b0f = bsh[o], b1f = bsh[o + 1];
            if (node0 < N) *(float2*)&g_rb2[node0 * NCLS + o] = make_float2(d[0] + b0f, d[1] + b1f);
            if (node1 < N) *(float2*)&g_rb2[node1 * NCLS + o] = make_float2(d[2] + b0f, d[3] + b1f);
        }
    }
}

// ---------------- layer-2 edge scatter: 6 edges/warp x 5 lanes, f16x2 red ---------
__global__ void __launch_bounds__(256) k_edge2(int E) {
    int t = blockIdx.x * blockDim.x + threadIdx.x;
    int lane = t & 31;
    int wid = t >> 5;
    int eg = lane / 5;
    int j  = lane - eg * 5;
    if (eg >= 6) return;
    long long e = (long long)wid * 6 + eg;
    if (e >= E) return;
    uint2 r = g_pack[e];
    int src = r.x & 0xffff;
    int dst = r.x >> 16;
    int k0  = r.y & 3;
    int k1  = min(k0 + 1, KS - 1);
    float f = __uint_as_float(r.y & ~3u);
    const __half* base = g_xw2h + src * 40;
    unsigned pa = *(const unsigned*)(base + k0 * 10 + j * 2);
    unsigned pb = *(const unsigned*)(base + k1 * 10 + j * 2);
    float2 A = __half22float2(*(const __half2*)&pa);
    float2 B = __half22float2(*(const __half2*)&pb);
    float w0 = 1.0f - f;
    __half2 h = __floats2half2_rn(w0 * A.x + f * B.x, w0 * A.y + f * B.y);
    red_add_h2(g_agg2h + dst * NCLS + j * 2, *(unsigned*)&h);
}

// ---------------- final: mean + root + bias + log_softmax -------------------------
__global__ void k_out(float* __restrict__ out, int N) {
    int n = blockIdx.x * blockDim.x + threadIdx.x;
    if (n >= N) return;
    float inv = 1.0f / fmaxf(g_deg[n], 1.0f);
    float v[NCLS];
    float mx = -1e30f;
    #pragma unroll
    for (int q = 0; q < NCLS / 2; q++) {
        unsigned aw = *(const unsigned*)&g_agg2h[n * NCLS + q * 2];
        float2 a  = __half22float2(*(const __half2*)&aw);
        float2 rb = *(const float2*)&g_rb2[n * NCLS + q * 2];
        v[q*2]   = a.x * inv + rb.x;
        v[q*2+1] = a.y * inv + rb.y;
        mx = fmaxf(mx, fmaxf(v[q*2], v[q*2+1]));
    }
    float s = 0.f;
    #pragma unroll
    for (int c = 0; c < NCLS; c++) s += expf(v[c] - mx);
    float ls = logf(s) + mx;
    float2* o2 = (float2*)&out[n * NCLS];
    #pragma unroll
    for (int q = 0; q < NCLS / 2; q++)
        o2[q] = make_float2(v[q*2] - ls, v[q*2+1] - ls);
}

// ---------------- launch -----------------------------------------------------------
extern "C" void kernel_launch(void* const* d_in, const int* in_sizes, int n_in,
                              void* d_out, int out_size) {
    const float* x     = (const float*)d_in[0];
    const void*  ei    =               d_in[1];
    const float* ea    = (const float*)d_in[2];
    const float* W1    = (const float*)d_in[3];
    const float* root1 = (const float*)d_in[4];
    const float* bias1 = (const float*)d_in[5];
    const float* W2    = (const float*)d_in[6];
    const float* root2 = (const float*)d_in[7];
    const float* bias2 = (const float*)d_in[8];
    float* out = (float*)d_out;

    int N = in_sizes[0] / FIN;     // 50000
    int E = in_sizes[2];           // 1600000

    int zgrid = (N * 22 + 255) / 256 + 1;
    k_init<<<zgrid, 256>>>(ei, W1, root1, W2, root2, N);
    int xwblocks = (N + 127) / 128;
    int packblocks = (E / 2 + 256) / 256;
    k_main1<<<xwblocks + packblocks, 256>>>(x, bias1, ei, ea, N, E, xwblocks);
    long long th1 = (long long)E * 4;
    k_edge1<<<(int)((th1 + 255) / 256), 256>>>(E);
    k_prep2<<<(N + 63) / 64, 128>>>(bias2, N);
    int warps2 = (E + 5) / 6;
    k_edge2<<<(warps2 + 7) / 8, 256>>>(E);
    k_out<<<(N + 255) / 256, 256>>>(out, N);
}

// round 15
// speedup vs baseline: 4.9161x; 1.0108x over previous
#include <cuda_runtime.h>
#include <cuda_fp16.h>
#include <cstdint>

#define MAXN  50000
#define MAXNP 50048          // padded to 128-node tile multiple (OOB-safe zero stores)
#define MAXE  1600000
#define FIN   48
#define HID   32
#define NCLS  10
#define KS    4

// ---------------- scratch (device globals; padded) --------------------------------
__device__ __half    g_xw1h[MAXNP * KS * HID];  // [N][4][32] fp16
__device__ float     g_rb1 [MAXNP * HID];       // x@root1 + bias1 (fp32)
__device__ __half    g_xw2h[MAXNP * KS * NCLS]; // [N][4][10] fp16
__device__ float     g_rb2 [MAXNP * NCLS];
__device__ __align__(16) __half g_agg1h[MAXNP * HID];
__device__ __align__(8)  __half g_agg2h[MAXNP * NCLS];
__device__ float     g_deg [MAXNP];
__device__ uint2     g_pack[MAXE];              // x: src|dst<<16,  y: frac-bits|k0
__device__ __half    g_wt1h[160 * FIN];         // W1^T+root1^T fp16 [160][48]
__device__ __half    g_wt2h[56 * HID];          // W2^T+root2^T fp16 [56][32]
__device__ int       g_is64;

// ---------------- helpers ---------------------------------------------------------
__device__ __forceinline__ void red_add_v4h2(__half* addr, uint4 v) {
    asm volatile("red.global.add.noftz.v4.f16x2 [%0], {%1,%2,%3,%4};"
                 :: "l"(addr), "r"(v.x), "r"(v.y), "r"(v.z), "r"(v.w) : "memory");
}
__device__ __forceinline__ void red_add_h2(__half* addr, unsigned v) {
    asm volatile("red.global.add.noftz.f16x2 [%0], %1;"
                 :: "l"(addr), "r"(v) : "memory");
}
__device__ __forceinline__ void mma16816(float* d, const unsigned* a,
                                         unsigned b0, unsigned b1) {
    asm("mma.sync.aligned.m16n8k16.row.col.f32.f16.f16.f32 "
        "{%0,%1,%2,%3}, {%4,%5,%6,%7}, {%8,%9}, {%0,%1,%2,%3};"
        : "+f"(d[0]), "+f"(d[1]), "+f"(d[2]), "+f"(d[3])
        : "r"(a[0]), "r"(a[1]), "r"(a[2]), "r"(a[3]), "r"(b0), "r"(b1));
}
__device__ __forceinline__ uint2 enc_edge(int src, int dst, float u) {
    float vv = u * (float)(KS - 1);
    float vf = floorf(vv);
    float frac = vv - vf;
    int k0 = min(max((int)vf, 0), KS - 1);
    return make_uint2((unsigned)src | ((unsigned)dst << 16),
                      (__float_as_uint(frac) & ~3u) | (unsigned)k0);
}

// ---------------- init: detect + wprep (block 0) + deg zero (other blocks) --------
__global__ void k_init(const void* __restrict__ ei,
                       const float* __restrict__ W1, const float* __restrict__ root1,
                       const float* __restrict__ W2, const float* __restrict__ root2,
                       int N) {
    if (blockIdx.x == 0) {
        if (threadIdx.x < 32) {
            int hi = ((const int*)ei)[2 * threadIdx.x + 1];
            unsigned b = __ballot_sync(0xffffffffu, hi != 0);
            if (threadIdx.x == 0) g_is64 = (b == 0) ? 1 : 0;
        }
        for (int i = threadIdx.x; i < 160 * FIN; i += 256) {
            int j = i / FIN, f = i % FIN;
            float v = (j < 128) ? W1[(((j >> 5) * FIN) + f) * HID + (j & 31)]
                                : root1[f * HID + (j - 128)];
            g_wt1h[i] = __float2half(v);
        }
        for (int i = threadIdx.x; i < 56 * HID; i += 256) {
            int c = i / HID, o = i % HID;
            float v = 0.f;
            if (c < 40)      { int k = c / NCLS, cc = c % NCLS; v = W2[(k * HID + o) * NCLS + cc]; }
            else if (c < 50) v = root2[o * NCLS + (c - 40)];
            g_wt2h[i] = __float2half(v);
        }
    } else {
        for (int i = (blockIdx.x - 1) * 256 + threadIdx.x; i < MAXNP;
             i += (gridDim.x - 1) * 256)
            g_deg[i] = 0.f;
    }
}

// ---------------- fused: xw1 HMMA + agg1h zero (blocks < xwblocks) + edge pack ----
__global__ void __launch_bounds__(256) k_main1(const float* __restrict__ x,
                                               const float* __restrict__ bias1,
                                               const void* __restrict__ ei,
                                               const float* __restrict__ ea,
                                               int N, int E, int xwblocks) {
    __shared__ __align__(16) __half xs[128 * 56];   // 14336 B
    __shared__ __align__(16) __half wt[160 * 56];   // 17920 B
    __shared__ float bsh[HID];
    const int tid = threadIdx.x;

    if (blockIdx.x >= xwblocks) {
        int b = blockIdx.x - xwblocks;
        long long e0 = ((long long)b * 256 + tid) * 2;
        if (e0 >= E) return;
        bool vec = ((E & 1) == 0) && (e0 + 1 < E);
        if (vec) {
            int src0, dst0, src1, dst1;
            if (g_is64) {
                longlong2 s = *(const longlong2*)((const long long*)ei + e0);
                longlong2 d = *(const longlong2*)((const long long*)ei + E + e0);
                src0 = (int)s.x; src1 = (int)s.y; dst0 = (int)d.x; dst1 = (int)d.y;
            } else {
                int2 s = *(const int2*)((const int*)ei + e0);
                int2 d = *(const int2*)((const int*)ei + E + e0);
                src0 = s.x; src1 = s.y; dst0 = d.x; dst1 = d.y;
            }
            float2 u = *(const float2*)(ea + e0);
            uint2 r0 = enc_edge(src0, dst0, u.x);
            uint2 r1 = enc_edge(src1, dst1, u.y);
            *(uint4*)&g_pack[e0] = make_uint4(r0.x, r0.y, r1.x, r1.y);
            atomicAdd(&g_deg[dst0], 1.0f);
            atomicAdd(&g_deg[dst1], 1.0f);
        } else {
            for (long long e = e0; e < e0 + 2 && e < E; e++) {
                int src, dst;
                if (g_is64) {
                    src = (int)((const long long*)ei)[e];
                    dst = (int)((const long long*)ei)[E + e];
                } else {
                    src = ((const int*)ei)[e];
                    dst = ((const int*)ei)[E + e];
                }
                g_pack[e] = enc_edge(src, dst, ea[e]);
                atomicAdd(&g_deg[dst], 1.0f);
            }
        }
        return;
    }

    // zero this block's 128-node slice of agg1h (8KB; in-bounds via MAXNP padding)
    int nbase = blockIdx.x * 128;
    {
        uint4 z = make_uint4(0, 0, 0, 0);
        uint4* dst = (uint4*)&g_agg1h[nbase * HID];   // 512 uint4
        for (int i = tid; i < 512; i += 256) dst[i] = z;
    }

    // xw1 HMMA
    for (int i2 = tid; i2 < 160 * (FIN / 2); i2 += 256) {
        int j = i2 / (FIN / 2), fp = i2 % (FIN / 2);
        *(__half2*)&wt[j * 56 + fp * 2] = ((const __half2*)g_wt1h)[i2];
    }
    if (tid < HID) bsh[tid] = bias1[tid];
    for (int i = tid; i < 128 * (FIN / 2); i += 256) {
        int nn = i / (FIN / 2), fp = i % (FIN / 2);
        int n = nbase + nn;
        float2 v = (n < N) ? *(const float2*)&x[(long long)n * FIN + fp * 2]
                           : make_float2(0.f, 0.f);
        *(__half2*)&xs[nn * 56 + fp * 2] = __floats2half2_rn(v.x, v.y);
    }
    __syncthreads();

    const int warp = tid >> 5;
    const int lane = tid & 31;
    const int g = lane >> 2;
    const int t = lane & 3;
    const int wn = warp * 16;

    unsigned a[3][4];
    #pragma unroll
    for (int kc = 0; kc < 3; kc++) {
        int k0 = kc * 16;
        a[kc][0] = *(const unsigned*)&xs[(wn + g)     * 56 + k0 + 2 * t];
        a[kc][1] = *(const unsigned*)&xs[(wn + g + 8) * 56 + k0 + 2 * t];
        a[kc][2] = *(const unsigned*)&xs[(wn + g)     * 56 + k0 + 2 * t + 8];
        a[kc][3] = *(const unsigned*)&xs[(wn + g + 8) * 56 + k0 + 2 * t + 8];
    }
    int node0 = nbase + wn + g;
    int node1 = node0 + 8;
    #pragma unroll
    for (int nt = 0; nt < 20; nt++) {
        int n0 = nt * 8;
        float d[4] = {0.f, 0.f, 0.f, 0.f};
        #pragma unroll
        for (int kc = 0; kc < 3; kc++) {
            unsigned b0 = *(const unsigned*)&wt[(n0 + g) * 56 + kc * 16 + 2 * t];
            unsigned b1 = *(const unsigned*)&wt[(n0 + g) * 56 + kc * 16 + 2 * t + 8];
            mma16816(d, a[kc], b0, b1);
        }
        int col = n0 + 2 * t;
        if (col < 128) {
            if (node0 < N) *(__half2*)&g_xw1h[node0 * 128 + col] = __floats2half2_rn(d[0], d[1]);
            if (node1 < N) *(__half2*)&g_xw1h[node1 * 128 + col] = __floats2half2_rn(d[2], d[3]);
        } else {
            int o = col - 128;
            float b0f = bsh[o], b1f = bsh[o + 1];
            if (node0 < N) *(float2*)&g_rb1[node0 * HID + o] = make_float2(d[0] + b0f, d[1] + b1f);
            if (node1 < N) *(float2*)&g_rb1[node1 * HID + o] = make_float2(d[2] + b0f, d[3] + b1f);
        }
    }
}

// ---------------- layer-1 edge scatter: 4 lanes/edge, uint4 gather, f16x2 red -----
__global__ void __launch_bounds__(256) k_edge1(int E) {
    long long t = (long long)blockIdx.x * blockDim.x + threadIdx.x;
    long long e = t >> 2;
    int j = (int)(t & 3);           // 8 features per lane
    if (e >= E) return;
    uint2 r = g_pack[e];
    int src = r.x & 0xffff;
    int dst = r.x >> 16;
    int k0  = r.y & 3;
    int k1  = min(k0 + 1, KS - 1);
    float f = __uint_as_float(r.y & ~3u);
    const __half* base = g_xw1h + src * 128;
    uint4 pa = *(const uint4*)(base + k0 * 32 + j * 8);
    uint4 pb = *(const uint4*)(base + k1 * 32 + j * 8);
    float w0 = 1.0f - f;
    uint4 o;
    #pragma unroll
    for (int q = 0; q < 4; q++) {
        float2 A = __half22float2(((const __half2*)&pa)[q]);
        float2 B = __half22float2(((const __half2*)&pb)[q]);
        __half2 h = __floats2half2_rn(w0 * A.x + f * B.x, w0 * A.y + f * B.y);
        ((__half2*)&o)[q] = h;
    }
    red_add_v4h2(g_agg1h + dst * HID + j * 8, o);
}

// ---------------- layer-2 node GEMM (128-node tiles) + ELU + agg2h zero ------------
__global__ void __launch_bounds__(256) k_prep2(const float* __restrict__ bias2, int N) {
    __shared__ __align__(16) __half hs[128 * 40];   // 10240 B
    __shared__ __align__(16) __half wt[56 * 40];    // 4480 B
    __shared__ float bsh[NCLS];
    const int tid = threadIdx.x;
    int nbase = blockIdx.x * 128;
    // zero this block's agg2h slice (640 words; in-bounds via MAXNP padding)
    {
        unsigned* dst = (unsigned*)&g_agg2h[nbase * NCLS];
        for (int i = tid; i < 640; i += 256) dst[i] = 0u;
    }
    for (int i2 = tid; i2 < 56 * (HID / 2); i2 += 256) {
        int c = i2 / (HID / 2), op = i2 % (HID / 2);
        *(__half2*)&wt[c * 40 + op * 2] = ((const __half2*)g_wt2h)[i2];
    }
    if (tid < NCLS) bsh[tid] = bias2[tid];
    for (int i = tid; i < 128 * (HID / 4); i += 256) {
        int nn = i / (HID / 4), q = i % (HID / 4);
        int n = nbase + nn;
        float4 h4 = make_float4(0.f, 0.f, 0.f, 0.f);
        if (n < N) {
            float inv = 1.0f / fmaxf(g_deg[n], 1.0f);
            uint2 ah = *(const uint2*)&g_agg1h[n * HID + q * 4];
            float2 a01 = __half22float2(*(const __half2*)&ah.x);
            float2 a23 = __half22float2(*(const __half2*)&ah.y);
            float4 rb = *(const float4*)&g_rb1[n * HID + q * 4];
            float v0 = a01.x * inv + rb.x, v1 = a01.y * inv + rb.y;
            float v2 = a23.x * inv + rb.z, v3 = a23.y * inv + rb.w;
            h4.x = (v0 > 0.f) ? v0 : expm1f(v0);
            h4.y = (v1 > 0.f) ? v1 : expm1f(v1);
            h4.z = (v2 > 0.f) ? v2 : expm1f(v2);
            h4.w = (v3 > 0.f) ? v3 : expm1f(v3);
        }
        *(__half2*)&hs[nn * 40 + q * 4]     = __floats2half2_rn(h4.x, h4.y);
        *(__half2*)&hs[nn * 40 + q * 4 + 2] = __floats2half2_rn(h4.z, h4.w);
    }
    __syncthreads();

    const int warp = tid >> 5;
    const int lane = tid & 31;
    const int g = lane >> 2;
    const int t = lane & 3;
    const int wn = warp * 16;

    unsigned a[2][4];
    #pragma unroll
    for (int kc = 0; kc < 2; kc++) {
        int k0 = kc * 16;
        a[kc][0] = *(const unsigned*)&hs[(wn + g)     * 40 + k0 + 2 * t];
        a[kc][1] = *(const unsigned*)&hs[(wn + g + 8) * 40 + k0 + 2 * t];
        a[kc][2] = *(const unsigned*)&hs[(wn + g)     * 40 + k0 + 2 * t + 8];
        a[kc][3] = *(const unsigned*)&hs[(wn + g + 8) * 40 + k0 + 2 * t + 8];
    }
    int node0 = nbase + wn + g;
    int node1 = node0 + 8;
    #pragma unroll
    for (int nt = 0; nt < 7; nt++) {
        int n0 = nt * 8;
        float d[4] = {0.f, 0.f, 0.f, 0.f};
        #pragma unroll
        for (int kc = 0; kc < 2; kc++) {
            unsigned b0 = *(const unsigned*)&wt[(n0 + g) * 40 + kc * 16 + 2 * t];
            unsigned b1 = *(const unsigned*)&wt[(n0 + g) * 40 + kc * 16 + 2 * t + 8];
            mma16816(d, a[kc], b0, b1);
        }
        int col = n0 + 2 * t;
        if (col < 40) {
            if (node0 < N) *(__half2*)&g_xw2h[node0 * 40 + col] = __floats2half2_rn(d[0], d[1]);
            if (node1 < N) *(__half2*)&g_xw2h[node1 * 40 + col] = __floats2half2_rn(d[2], d[3]);
        } else if (col < 50) {
            int o = col - 40;
            float b0f = bsh[o], b1f = bsh[o + 1];
            if (node0 < N) *(float2*)&g_rb2[node0 * NCLS + o] = make_float2(d[0] + b0f, d[1] + b1f);
            if (node1 < N) *(float2*)&g_rb2[node1 * NCLS + o] = make_float2(d[2] + b0f, d[3] + b1f);
        }
    }
}

// ---------------- layer-2 edge scatter: 6 edges/warp x 5 lanes, f16x2 red ---------
__global__ void __launch_bounds__(256) k_edge2(int E) {
    int t = blockIdx.x * blockDim.x + threadIdx.x;
    int lane = t & 31;
    int wid = t >> 5;
    int eg = lane / 5;
    int j  = lane - eg * 5;
    if (eg >= 6) return;
    long long e = (long long)wid * 6 + eg;
    if (e >= E) return;
    uint2 r = g_pack[e];
    int src = r.x & 0xffff;
    int dst = r.x >> 16;
    int k0  = r.y & 3;
    int k1  = min(k0 + 1, KS - 1);
    float f = __uint_as_float(r.y & ~3u);
    const __half* base = g_xw2h + src * 40;
    unsigned pa = *(const unsigned*)(base + k0 * 10 + j * 2);
    unsigned pb = *(const unsigned*)(base + k1 * 10 + j * 2);
    float2 A = __half22float2(*(const __half2*)&pa);
    float2 B = __half22float2(*(const __half2*)&pb);
    float w0 = 1.0f - f;
    __half2 h = __floats2half2_rn(w0 * A.x + f * B.x, w0 * A.y + f * B.y);
    red_add_h2(g_agg2h + dst * NCLS + j * 2, *(unsigned*)&h);
}

// ---------------- final: mean + root + bias + log_softmax -------------------------
__global__ void k_out(float* __restrict__ out, int N) {
    int n = blockIdx.x * blockDim.x + threadIdx.x;
    if (n >= N) return;
    float inv = 1.0f / fmaxf(g_deg[n], 1.0f);
    float v[NCLS];
    float mx = -1e30f;
    #pragma unroll
    for (int q = 0; q < NCLS / 2; q++) {
        unsigned aw = *(const unsigned*)&g_agg2h[n * NCLS + q * 2];
        float2 a  = __half22float2(*(const __half2*)&aw);
        float2 rb = *(const float2*)&g_rb2[n * NCLS + q * 2];
        v[q*2]   = a.x * inv + rb.x;
        v[q*2+1] = a.y * inv + rb.y;
        mx = fmaxf(mx, fmaxf(v[q*2], v[q*2+1]));
    }
    float s = 0.f;
    #pragma unroll
    for (int c = 0; c < NCLS; c++) s += expf(v[c] - mx);
    float ls = logf(s) + mx;
    float2* o2 = (float2*)&out[n * NCLS];
    #pragma unroll
    for (int q = 0; q < NCLS / 2; q++)
        o2[q] = make_float2(v[q*2] - ls, v[q*2+1] - ls);
}

// ---------------- launch -----------------------------------------------------------
extern "C" void kernel_launch(void* const* d_in, const int* in_sizes, int n_in,
                              void* d_out, int out_size) {
    const float* x     = (const float*)d_in[0];
    const void*  ei    =               d_in[1];
    const float* ea    = (const float*)d_in[2];
    const float* W1    = (const float*)d_in[3];
    const float* root1 = (const float*)d_in[4];
    const float* bias1 = (const float*)d_in[5];
    const float* W2    = (const float*)d_in[6];
    const float* root2 = (const float*)d_in[7];
    const float* bias2 = (const float*)d_in[8];
    float* out = (float*)d_out;

    int N = in_sizes[0] / FIN;     // 50000
    int E = in_sizes[2];           // 1600000

    k_init<<<(MAXNP + 255) / 256 + 1, 256>>>(ei, W1, root1, W2, root2, N);
    int xwblocks = (N + 127) / 128;
    int packblocks = (E / 2 + 256) / 256;
    k_main1<<<xwblocks + packblocks, 256>>>(x, bias1, ei, ea, N, E, xwblocks);
    long long th1 = (long long)E * 4;
    k_edge1<<<(int)((th1 + 255) / 256), 256>>>(E);
    k_prep2<<<(N + 127) / 128, 256>>>(bias2, N);
    int warps2 = (E + 5) / 6;
    k_edge2<<<(warps2 + 7) / 8, 256>>>(E);
    k_out<<<(N + 255) / 256, 256>>>(out, N);
}